// round 1
// baseline (speedup 1.0000x reference)
#include <cuda_runtime.h>
#include <math.h>

#define Bn 8
#define Cc 64
#define Hh 128
#define Ww 128
#define Gg 4
#define CG 16
#define HW (Hh*Ww)          // 16384
#define CHW (Cc*HW)         // 1048576
#define SZ (Bn*CHW)         // 8388608
#define NR (Bn*Hh)          // 1024
#define SZM (NR*Ww*Ww)      // 16777216
#define TH 8

// scratch (device globals; no allocation allowed)
__device__ float g_t[2*SZ];        // conv1+lrelu outputs
__device__ float g_r[2*SZ];        // resblock outputs
__device__ float g_qk[2*SZ];       // Q (side0) / K (side1), mean-subtracted
__device__ float g_M[2*SZM];       // M_rl (0), M_lr (1)
__device__ float g_V[2*NR*Ww];     // tanh(5*V_left), tanh(5*V_right)
__device__ float g_stats[2][2][Cc];// [side][a|d][c]: bn(x) = a*x + d

// ---------------- BN batch statistics ----------------
__global__ void __launch_bounds__(256) k_bnstats(const float* __restrict__ xl,
                                                 const float* __restrict__ xr,
                                                 const float* __restrict__ gamma,
                                                 const float* __restrict__ beta) {
    int c = blockIdx.x, side = blockIdx.y;
    const float* x = side ? xr : xl;
    int tid = threadIdx.x;
    double s = 0.0, s2 = 0.0;
    for (int b = 0; b < Bn; b++) {
        const float* p = x + b*CHW + c*HW;
        for (int i = tid; i < HW; i += 256) {
            float v = p[i];
            s += v; s2 += (double)v * v;
        }
    }
    __shared__ double sh[256], sh2[256];
    sh[tid] = s; sh2[tid] = s2;
    __syncthreads();
    for (int off = 128; off; off >>= 1) {
        if (tid < off) { sh[tid] += sh[tid+off]; sh2[tid] += sh2[tid+off]; }
        __syncthreads();
    }
    if (tid == 0) {
        double N = (double)(Bn*HW);
        double m = sh[0] / N;
        double var = sh2[0] / N - m*m;
        double rstd = 1.0 / sqrt(var + 1e-5);
        float a = gamma[c] * (float)rstd;
        float d = beta[c] - a * (float)m;
        g_stats[side][0][c] = a;
        g_stats[side][1][c] = d;
    }
}

// ---------------- grouped 3x3 conv ----------------
// FIRST:  out = lrelu(conv3(bn(x)))            (bn applied during load)
// !FIRST: out = conv3(t) + bias + bn(x)        (residual fused in epilogue)
template<bool FIRST>
__global__ void __launch_bounds__(256) k_conv3(const float* __restrict__ xl,
                                               const float* __restrict__ xr,
                                               const float* __restrict__ wgt,
                                               const float* __restrict__ bias) {
    int ty = blockIdx.x, g = blockIdx.y;
    int side = blockIdx.z >> 3, b = blockIdx.z & 7;
    const float* xraw = side ? xr : xl;
    const float* in   = FIRST ? xraw : (g_t + side*SZ);
    float* out        = FIRST ? (g_t + side*SZ) : (g_r + side*SZ);

    extern __shared__ float sm[];
    float* sIn = sm;                      // [CG][TH+2][130]
    float* sW  = sm + CG*(TH+2)*130;      // [16][16][9]
    __shared__ float sa[CG], sd[CG];
    int tid = threadIdx.x;

    if (tid < CG) {
        sa[tid] = g_stats[side][0][g*CG + tid];
        sd[tid] = g_stats[side][1][g*CG + tid];
    }
    __syncthreads();

    for (int i = tid; i < CG*CG*9; i += 256) sW[i] = wgt[g*CG*CG*9 + i];

    int y0 = ty*TH - 1;
    const float* inb = in + b*CHW + g*CG*HW;
    for (int idx = tid; idx < CG*(TH+2)*130; idx += 256) {
        int ic  = idx / ((TH+2)*130);
        int rem = idx - ic*(TH+2)*130;
        int r   = rem / 130;
        int xx  = rem - r*130 - 1;
        int yy  = y0 + r;
        float v = 0.f;
        if ((unsigned)yy < (unsigned)Hh && (unsigned)xx < (unsigned)Ww) {
            v = inb[ic*HW + yy*Ww + xx];
            if (FIRST) v = fmaf(sa[ic], v, sd[ic]);
        }
        sIn[idx] = v;
    }
    __syncthreads();

    int xcol = tid & 127, half = tid >> 7;
    float acc[8][TH];
#pragma unroll
    for (int o = 0; o < 8; o++) {
        float bv = bias[g*CG + half*8 + o];
#pragma unroll
        for (int r = 0; r < TH; r++) acc[o][r] = bv;
    }

    for (int ic = 0; ic < CG; ic++) {
        const float* ip = sIn + ic*(TH+2)*130;
        const float* wp = sW + (half*8)*CG*9 + ic*9;
#pragma unroll
        for (int k = 0; k < 9; k++) {
            int dy = k / 3, dx = k - dy*3;
            float wk[8];
#pragma unroll
            for (int o = 0; o < 8; o++) wk[o] = wp[o*CG*9 + k];
#pragma unroll
            for (int r = 0; r < TH; r++) {
                float iv = ip[(r+dy)*130 + xcol + dx];
#pragma unroll
                for (int o = 0; o < 8; o++) acc[o][r] = fmaf(wk[o], iv, acc[o][r]);
            }
        }
    }

    int ybase = ty*TH;
#pragma unroll
    for (int o = 0; o < 8; o++) {
        int ocl = half*8 + o;
        int oc = g*CG + ocl;
        int gbase = b*CHW + oc*HW + ybase*Ww + xcol;
#pragma unroll
        for (int r = 0; r < TH; r++) {
            float v = acc[o][r];
            if (FIRST) {
                v = v > 0.f ? v : 0.1f*v;
            } else {
                float xv = xraw[gbase + r*Ww];
                v += fmaf(sa[ocl], xv, sd[ocl]);
            }
            out[gbase + r*Ww] = v;
        }
    }
}

// ---------------- grouped 1x1 Q/K conv + row-mean subtract ----------------
__global__ void __launch_bounds__(256) k_qk(const float* __restrict__ qw, const float* __restrict__ qb,
                                            const float* __restrict__ kw, const float* __restrict__ kb) {
    int h = blockIdx.x, b = blockIdx.y, side = blockIdx.z;
    const float* w  = side ? kw : qw;
    const float* bb = side ? kb : qb;
    const float* r = g_r + side*SZ + b*CHW + h*Ww;
    extern __shared__ float sm[];
    float* sR = sm;           // [64][128]
    float* sQ = sm + 8192;    // [64][128]
    float* sWt = sm + 16384;  // [64][16]
    float* sMean = sm + 17408;// [64]
    int tid = threadIdx.x;

    for (int idx = tid; idx < 8192; idx += 256) {
        int c = idx >> 7, x = idx & 127;
        sR[idx] = r[c*HW + x];
    }
    for (int idx = tid; idx < 1024; idx += 256) sWt[idx] = w[idx];
    __syncthreads();

    int x = tid & 127, half = tid >> 7;
    for (int oo = 0; oo < 32; oo++) {
        int o = half*32 + oo;
        int g = o >> 4;
        float acc = bb[o];
#pragma unroll
        for (int i = 0; i < 16; i++)
            acc = fmaf(sWt[o*16 + i], sR[(g*16 + i)*128 + x], acc);
        sQ[o*128 + x] = acc;
    }
    __syncthreads();

    int wrp = tid >> 5, lane = tid & 31;
    for (int o = wrp*8; o < wrp*8 + 8; o++) {
        float s = sQ[o*128 + lane] + sQ[o*128 + lane + 32]
                + sQ[o*128 + lane + 64] + sQ[o*128 + lane + 96];
        for (int off = 16; off; off >>= 1) s += __shfl_down_sync(0xffffffffu, s, off);
        s = __shfl_sync(0xffffffffu, s, 0);
        if (lane == 0) sMean[o] = s * (1.f/128.f);
    }
    __syncthreads();

    float* qout = g_qk + side*SZ + b*CHW + h*Ww;
    for (int oo = 0; oo < 32; oo++) {
        int o = half*32 + oo;
        qout[o*HW + x] = sQ[o*128 + x] - sMean[o];
    }
}

// ---------------- per-row score + dual softmax + validity ----------------
__global__ void __launch_bounds__(256) k_attn() {
    int n = blockIdx.x;
    int b = n >> 7, h = n & 127;
    extern __shared__ float sm[];
    float* sQ = sm;              // [128][65]
    float* sK = sm + 128*65;     // [64][132]
    float* sS = sm + 16768;      // [128][129]
    float* sM = sm;              // [128][129] overlays sQ+sK (dead after GEMM)
    __shared__ float rmax[128], rinv[128], cmax[128], cinv[128];
    int tid = threadIdx.x;

    const float* Qg = g_qk + b*CHW + h*Ww;
    const float* Kg = g_qk + SZ + b*CHW + h*Ww;
    for (int idx = tid; idx < 8192; idx += 256) {
        int c = idx >> 7, u = idx & 127;
        float qv = Qg[c*HW + u];
        float kv = Kg[c*HW + u];
        sQ[u*65 + c]  = qv;
        sK[c*132 + u] = kv;
    }
    __syncthreads();

    int lane = tid & 31, wrp = tid >> 5;
    int v0 = wrp*16;
    float acc[4][16];
#pragma unroll
    for (int i = 0; i < 4; i++)
#pragma unroll
        for (int j = 0; j < 16; j++) acc[i][j] = 0.f;

    for (int c = 0; c < 64; c++) {
        float a0 = sQ[lane*65 + c];
        float a1 = sQ[(lane+32)*65 + c];
        float a2 = sQ[(lane+64)*65 + c];
        float a3 = sQ[(lane+96)*65 + c];
        const float4* kp = (const float4*)(sK + c*132 + v0);
        float4 q0 = kp[0], q1 = kp[1], q2 = kp[2], q3 = kp[3];
        float bv[16] = {q0.x,q0.y,q0.z,q0.w, q1.x,q1.y,q1.z,q1.w,
                        q2.x,q2.y,q2.z,q2.w, q3.x,q3.y,q3.z,q3.w};
#pragma unroll
        for (int j = 0; j < 16; j++) {
            acc[0][j] = fmaf(a0, bv[j], acc[0][j]);
            acc[1][j] = fmaf(a1, bv[j], acc[1][j]);
            acc[2][j] = fmaf(a2, bv[j], acc[2][j]);
            acc[3][j] = fmaf(a3, bv[j], acc[3][j]);
        }
    }
#pragma unroll
    for (int i = 0; i < 4; i++)
#pragma unroll
        for (int j = 0; j < 16; j++)
            sS[(lane + 32*i)*129 + v0 + j] = acc[i][j];
    __syncthreads();

    // softmax statistics: rows (tid<128) and columns (tid>=128)
    if (tid < 128) {
        int u = tid; float m = -1e30f;
        for (int v = 0; v < 128; v++) m = fmaxf(m, sS[u*129 + v]);
        float s = 0.f;
        for (int v = 0; v < 128; v++) s += __expf(sS[u*129 + v] - m);
        rmax[u] = m; rinv[u] = 1.f / s;
    } else {
        int u = tid - 128; float m = -1e30f;
        for (int v = 0; v < 128; v++) m = fmaxf(m, sS[v*129 + u]);
        float s = 0.f;
        for (int v = 0; v < 128; v++) s += __expf(sS[v*129 + u] - m);
        cmax[u] = m; cinv[u] = 1.f / s;
    }
    __syncthreads();

    // M_rl into sM (overlay) + global
    float* Mrl = g_M + (long)n*16384;
    for (int idx = tid; idx < 16384; idx += 256) {
        int u = idx >> 7, v = idx & 127;
        float val = __expf(sS[u*129 + v] - rmax[u]) * rinv[u];
        sM[u*129 + v] = val;
        Mrl[idx] = val;
    }
    __syncthreads();

    // in-place: sS[r][u] <- exp(S[r][u]-cmax[u])*cinv[u]  ( = M_lr[u][r] )
    for (int idx = tid; idx < 16384; idx += 256) {
        int rr = idx >> 7, uu = idx & 127;
        sS[rr*129 + uu] = __expf(sS[rr*129 + uu] - cmax[uu]) * cinv[uu];
    }
    __syncthreads();

    // M_lr global: Mlr[u][v] = sS[v][u]
    float* Mlr = g_M + SZM + (long)n*16384;
    for (int idx = tid; idx < 16384; idx += 256) {
        int u = idx >> 7, v = idx & 127;
        Mlr[idx] = sS[v*129 + u];
    }

    // validity maps
    if (tid < 128) {
        int u = tid;
        float accv = 0.f;
        for (int v = 0; v < 128; v++) {
            float A = 0.f;
#pragma unroll
            for (int d = -2; d <= 2; d++) {
                int uu = u + d;
                if ((unsigned)uu < 128u) A += sM[uu*129 + v];
            }
            accv += A * sS[u*129 + v];   // * M_lr[v][u]
        }
        g_V[(long)n*128 + u] = tanhf(5.f * accv);
    } else {
        int u = tid - 128;
        float accv = 0.f;
        for (int v = 0; v < 128; v++) {
            float A = 0.f;
#pragma unroll
            for (int d = -2; d <= 2; d++) {
                int uu = u + d;
                if ((unsigned)uu < 128u) A += sS[v*129 + uu];  // M_lr[u+d][v]
            }
            accv += A * sM[v*129 + u];   // * M_rl[v][u]
        }
        g_V[NR*Ww + (long)n*128 + u] = tanhf(5.f * accv);
    }
}

// ---------------- transport + blend ----------------
__global__ void __launch_bounds__(256) k_transport(const float* __restrict__ xl,
                                                   const float* __restrict__ xr,
                                                   float* __restrict__ out) {
    int n = blockIdx.x, side = blockIdx.y;
    int b = n >> 7, h = n & 127;
    const float* M   = g_M + (long)side*SZM + (long)n*16384;
    const float* src  = side ? xl : xr;
    const float* base = side ? xr : xl;
    extern __shared__ float sm[];
    float* sMt = sm;           // [128][129]
    float* sX  = sm + 16512;   // [128][68]
    __shared__ float sV[128];
    int tid = threadIdx.x;

    for (int idx = tid; idx < 16384; idx += 256)
        sMt[(idx >> 7)*129 + (idx & 127)] = M[idx];
    for (int idx = tid; idx < 8192; idx += 256) {
        int c = idx >> 7, v = idx & 127;
        sX[v*68 + c] = src[b*CHW + c*HW + h*Ww + v];
    }
    if (tid < 128) sV[tid] = g_V[(long)side*NR*Ww + (long)n*128 + tid];
    __syncthreads();

    int lane = tid & 31, wrp = tid >> 5;
    int c0 = wrp*8;
    float acc[4][8];
#pragma unroll
    for (int i = 0; i < 4; i++)
#pragma unroll
        for (int j = 0; j < 8; j++) acc[i][j] = 0.f;

    for (int v = 0; v < 128; v++) {
        float a0 = sMt[lane*129 + v];
        float a1 = sMt[(lane+32)*129 + v];
        float a2 = sMt[(lane+64)*129 + v];
        float a3 = sMt[(lane+96)*129 + v];
        const float4* xp = (const float4*)(sX + v*68 + c0);
        float4 x0 = xp[0], x1 = xp[1];
        float bv[8] = {x0.x,x0.y,x0.z,x0.w, x1.x,x1.y,x1.z,x1.w};
#pragma unroll
        for (int j = 0; j < 8; j++) {
            acc[0][j] = fmaf(a0, bv[j], acc[0][j]);
            acc[1][j] = fmaf(a1, bv[j], acc[1][j]);
            acc[2][j] = fmaf(a2, bv[j], acc[2][j]);
            acc[3][j] = fmaf(a3, bv[j], acc[3][j]);
        }
    }

    float* ob = out + (long)side*SZ + b*CHW + h*Ww;
    const float* bb = base + b*CHW + h*Ww;
#pragma unroll
    for (int i = 0; i < 4; i++) {
        int u = lane + 32*i;
        float Vv = sV[u];
#pragma unroll
        for (int j = 0; j < 8; j++) {
            int c = c0 + j;
            float bvv = bb[c*HW + u];
            ob[c*HW + u] = fmaf(bvv, 1.f - Vv, acc[i][j]*Vv);
        }
    }
}

// ---------------- launcher ----------------
extern "C" void kernel_launch(void* const* d_in, const int* in_sizes, int n_in,
                              void* d_out, int out_size) {
    const float* xl    = (const float*)d_in[0];
    const float* xr    = (const float*)d_in[1];
    const float* gamma = (const float*)d_in[2];
    const float* beta  = (const float*)d_in[3];
    const float* rw1   = (const float*)d_in[4];
    const float* rb1   = (const float*)d_in[5];
    const float* rw2   = (const float*)d_in[6];
    const float* rb2   = (const float*)d_in[7];
    const float* qw    = (const float*)d_in[8];
    const float* qb    = (const float*)d_in[9];
    const float* kw    = (const float*)d_in[10];
    const float* kb    = (const float*)d_in[11];
    float* out = (float*)d_out;

    const int CONV_SMEM = (CG*(TH+2)*130 + CG*CG*9) * 4;   // 92416
    const int QK_SMEM   = (8192 + 8192 + 1024 + 64) * 4;   // 69888
    const int ATTN_SMEM = (16768 + 16512) * 4;             // 133120
    const int TR_SMEM   = (16512 + 128*68) * 4;            // 100864

    cudaFuncSetAttribute(k_conv3<true>,  cudaFuncAttributeMaxDynamicSharedMemorySize, CONV_SMEM);
    cudaFuncSetAttribute(k_conv3<false>, cudaFuncAttributeMaxDynamicSharedMemorySize, CONV_SMEM);
    cudaFuncSetAttribute(k_qk,           cudaFuncAttributeMaxDynamicSharedMemorySize, QK_SMEM);
    cudaFuncSetAttribute(k_attn,         cudaFuncAttributeMaxDynamicSharedMemorySize, ATTN_SMEM);
    cudaFuncSetAttribute(k_transport,    cudaFuncAttributeMaxDynamicSharedMemorySize, TR_SMEM);

    k_bnstats<<<dim3(Cc, 2), 256>>>(xl, xr, gamma, beta);
    k_conv3<true ><<<dim3(Hh/TH, Gg, 2*Bn), 256, CONV_SMEM>>>(xl, xr, rw1, rb1);
    k_conv3<false><<<dim3(Hh/TH, Gg, 2*Bn), 256, CONV_SMEM>>>(xl, xr, rw2, rb2);
    k_qk<<<dim3(Hh, Bn, 2), 256, QK_SMEM>>>(qw, qb, kw, kb);
    k_attn<<<NR, 256, ATTN_SMEM>>>();
    k_transport<<<dim3(NR, 2), 256, TR_SMEM>>>(xl, xr, out);
}

// round 2
// speedup vs baseline: 1.1127x; 1.1127x over previous
#include <cuda_runtime.h>
#include <math.h>

#define Bn 8
#define Cc 64
#define Hh 128
#define Ww 128
#define Gg 4
#define CG 16
#define HW (Hh*Ww)          // 16384
#define CHW (Cc*HW)         // 1048576
#define SZ (Bn*CHW)         // 8388608
#define NR (Bn*Hh)          // 1024
#define TH 8

// scratch (device globals; no allocation allowed)
__device__ float g_t[2*SZ];        // conv1+lrelu outputs
__device__ float g_r[2*SZ];        // resblock outputs
__device__ float g_stats[2][2][Cc];// [side][a|d][c]: bn(x) = a*x + d

// ---------------- BN batch statistics ----------------
__global__ void __launch_bounds__(256) k_bnstats(const float* __restrict__ xl,
                                                 const float* __restrict__ xr,
                                                 const float* __restrict__ gamma,
                                                 const float* __restrict__ beta) {
    int c = blockIdx.x, side = blockIdx.y;
    const float* x = side ? xr : xl;
    int tid = threadIdx.x;
    double s = 0.0, s2 = 0.0;
    for (int b = 0; b < Bn; b++) {
        const float* p = x + b*CHW + c*HW;
        for (int i = tid; i < HW; i += 256) {
            float v = p[i];
            s += v; s2 += (double)v * v;
        }
    }
    __shared__ double sh[256], sh2[256];
    sh[tid] = s; sh2[tid] = s2;
    __syncthreads();
    for (int off = 128; off; off >>= 1) {
        if (tid < off) { sh[tid] += sh[tid+off]; sh2[tid] += sh2[tid+off]; }
        __syncthreads();
    }
    if (tid == 0) {
        double N = (double)(Bn*HW);
        double m = sh[0] / N;
        double var = sh2[0] / N - m*m;
        double rstd = 1.0 / sqrt(var + 1e-5);
        float a = gamma[c] * (float)rstd;
        float d = beta[c] - a * (float)m;
        g_stats[side][0][c] = a;
        g_stats[side][1][c] = d;
    }
}

// ---------------- grouped 3x3 conv ----------------
// FIRST:  out = lrelu(conv3(bn(x)))            (bn applied during load)
// !FIRST: out = conv3(t) + bias + bn(x)        (residual fused in epilogue)
template<bool FIRST>
__global__ void __launch_bounds__(256) k_conv3(const float* __restrict__ xl,
                                               const float* __restrict__ xr,
                                               const float* __restrict__ wgt,
                                               const float* __restrict__ bias) {
    int ty = blockIdx.x, g = blockIdx.y;
    int side = blockIdx.z >> 3, b = blockIdx.z & 7;
    const float* xraw = side ? xr : xl;
    const float* in   = FIRST ? xraw : (g_t + side*SZ);
    float* out        = FIRST ? (g_t + side*SZ) : (g_r + side*SZ);

    extern __shared__ float sm[];
    float* sIn = sm;                      // [CG][TH+2][130]
    float* sW  = sm + CG*(TH+2)*130;      // [16][16][9]
    __shared__ float sa[CG], sd[CG];
    int tid = threadIdx.x;

    if (tid < CG) {
        sa[tid] = g_stats[side][0][g*CG + tid];
        sd[tid] = g_stats[side][1][g*CG + tid];
    }
    __syncthreads();

    for (int i = tid; i < CG*CG*9; i += 256) sW[i] = wgt[g*CG*CG*9 + i];

    int y0 = ty*TH - 1;
    const float* inb = in + b*CHW + g*CG*HW;
    for (int idx = tid; idx < CG*(TH+2)*130; idx += 256) {
        int ic  = idx / ((TH+2)*130);
        int rem = idx - ic*(TH+2)*130;
        int r   = rem / 130;
        int xx  = rem - r*130 - 1;
        int yy  = y0 + r;
        float v = 0.f;
        if ((unsigned)yy < (unsigned)Hh && (unsigned)xx < (unsigned)Ww) {
            v = inb[ic*HW + yy*Ww + xx];
            if (FIRST) v = fmaf(sa[ic], v, sd[ic]);
        }
        sIn[idx] = v;
    }
    __syncthreads();

    int xcol = tid & 127, half = tid >> 7;
    float acc[8][TH];
#pragma unroll
    for (int o = 0; o < 8; o++) {
        float bv = bias[g*CG + half*8 + o];
#pragma unroll
        for (int r = 0; r < TH; r++) acc[o][r] = bv;
    }

    for (int ic = 0; ic < CG; ic++) {
        const float* ip = sIn + ic*(TH+2)*130;
        const float* wp = sW + (half*8)*CG*9 + ic*9;
#pragma unroll
        for (int k = 0; k < 9; k++) {
            int dy = k / 3, dx = k - dy*3;
            float wk[8];
#pragma unroll
            for (int o = 0; o < 8; o++) wk[o] = wp[o*CG*9 + k];
#pragma unroll
            for (int r = 0; r < TH; r++) {
                float iv = ip[(r+dy)*130 + xcol + dx];
#pragma unroll
                for (int o = 0; o < 8; o++) acc[o][r] = fmaf(wk[o], iv, acc[o][r]);
            }
        }
    }

    int ybase = ty*TH;
#pragma unroll
    for (int o = 0; o < 8; o++) {
        int ocl = half*8 + o;
        int oc = g*CG + ocl;
        int gbase = b*CHW + oc*HW + ybase*Ww + xcol;
#pragma unroll
        for (int r = 0; r < TH; r++) {
            float v = acc[o][r];
            if (FIRST) {
                v = v > 0.f ? v : 0.1f*v;
            } else {
                float xv = xraw[gbase + r*Ww];
                v += fmaf(sa[ocl], xv, sd[ocl]);
            }
            out[gbase + r*Ww] = v;
        }
    }
}

// ---------------- fused: QK 1x1 conv + score + dual softmax + validity + transport ----------------
// dynamic smem layout (floats):
//   sA  @0      : Q^T [128][65]     (8320)   \ overlaid later by sM [128][129]
//   sB  @8320   : K   [64][132]     (8448)   /
//   sS  @16768  : scores -> M_lr^T [128][129] (16512)  (first reused for R rows)
//   sXl @33280  : x_left  rows [v][68] (8704)
//   sXr @41984  : x_right rows [v][68] (8704)
#define ATT_SMEM (50688*4)
__global__ void __launch_bounds__(512) k_attn(const float* __restrict__ xl,
                                              const float* __restrict__ xr,
                                              const float* __restrict__ qw, const float* __restrict__ qb,
                                              const float* __restrict__ kw, const float* __restrict__ kb,
                                              float* __restrict__ out) {
    int n = blockIdx.x, b = n >> 7, h = n & 127;
    extern __shared__ float sm[];
    float* sA  = sm;
    float* sB  = sm + 8320;
    float* sS  = sm + 16768;
    float* sXl = sm + 33280;
    float* sXr = sm + 41984;
    float* sM  = sm;                 // overlay (sA+sB dead after score GEMM)
    __shared__ float sW[2048];
    __shared__ float sBias[128];
    __shared__ float sMean[128];
    __shared__ float rmax[128], rinv[128], cmax[128], cinv[128];
    __shared__ float sV[2][128];
    int tid = threadIdx.x, lane = tid & 31, w = tid >> 5;

    // ---- phase 0: load resblock rows (into sS region), x rows, weights
    const float* Rl = g_r + b*CHW + h*Ww;
    const float* Rr = g_r + SZ + b*CHW + h*Ww;
    float* sRl = sS;          // [c][128]
    float* sRr = sS + 8192;
    for (int idx = tid; idx < 8192; idx += 512) {
        int c = idx >> 7, x = idx & 127;
        sRl[idx] = Rl[c*HW + x];
        sRr[idx] = Rr[c*HW + x];
        sXl[x*68 + c] = xl[b*CHW + c*HW + h*Ww + x];
        sXr[x*68 + c] = xr[b*CHW + c*HW + h*Ww + x];
    }
    for (int idx = tid; idx < 1024; idx += 512) {
        sW[idx] = qw[idx]; sW[1024 + idx] = kw[idx];
    }
    if (tid < 64) { sBias[tid] = qb[tid]; sBias[64 + tid] = kb[tid]; }
    __syncthreads();

    // ---- phase 1: grouped 1x1 Q/K conv
    for (int t = tid; t < 16384; t += 512) {
        int side = t >> 13, rem = t & 8191, o = rem >> 7, x = rem & 127;
        int g = o >> 4;
        const float* R = side ? sRr : sRl;
        const float* wp = sW + side*1024 + o*16;
        float acc = sBias[side*64 + o];
#pragma unroll
        for (int i = 0; i < 16; i++)
            acc = fmaf(wp[i], R[(g*16 + i)*128 + x], acc);
        if (side == 0) sA[x*65 + o] = acc;
        else           sB[o*132 + x] = acc;
    }
    __syncthreads();

    // ---- phase 2: per-channel row means, subtract
    for (int task = w; task < 128; task += 16) {
        float s = 0.f;
        if (task < 64) {
#pragma unroll
            for (int k = 0; k < 4; k++) s += sA[(lane + 32*k)*65 + task];
        } else {
#pragma unroll
            for (int k = 0; k < 4; k++) s += sB[(task - 64)*132 + lane + 32*k];
        }
#pragma unroll
        for (int off = 16; off; off >>= 1) s += __shfl_xor_sync(0xffffffffu, s, off);
        if (lane == 0) sMean[task] = s * (1.f/128.f);
    }
    __syncthreads();
    for (int idx = tid; idx < 8192; idx += 512) {
        int c = idx >> 7, u = idx & 127;
        sA[u*65 + c]  -= sMean[c];
        sB[c*132 + u] -= sMean[64 + c];
    }
    __syncthreads();

    // ---- phase 3: score GEMM S[u][v] = sum_c Q[c][u] K[c][v]
    {
        int rh = w >> 3, v0 = (w & 7)*16;
        int u0 = lane + 64*rh, u1 = u0 + 32;
        float acc[2][16];
#pragma unroll
        for (int i = 0; i < 2; i++)
#pragma unroll
            for (int j = 0; j < 16; j++) acc[i][j] = 0.f;
        for (int c = 0; c < 64; c++) {
            float a0 = sA[u0*65 + c];
            float a1 = sA[u1*65 + c];
            const float4* kp = (const float4*)(sB + c*132 + v0);
            float4 q0 = kp[0], q1 = kp[1], q2 = kp[2], q3 = kp[3];
            float bv[16] = {q0.x,q0.y,q0.z,q0.w, q1.x,q1.y,q1.z,q1.w,
                            q2.x,q2.y,q2.z,q2.w, q3.x,q3.y,q3.z,q3.w};
#pragma unroll
            for (int j = 0; j < 16; j++) {
                acc[0][j] = fmaf(a0, bv[j], acc[0][j]);
                acc[1][j] = fmaf(a1, bv[j], acc[1][j]);
            }
        }
#pragma unroll
        for (int j = 0; j < 16; j++) {
            sS[u0*129 + v0 + j] = acc[0][j];
            sS[u1*129 + v0 + j] = acc[1][j];
        }
    }
    __syncthreads();

    // ---- phase 4: softmax stats, warp-parallel
    for (int r = w; r < 128; r += 16) {
        float v4[4]; float m = -1e30f;
#pragma unroll
        for (int k = 0; k < 4; k++) { v4[k] = sS[r*129 + lane + 32*k]; m = fmaxf(m, v4[k]); }
#pragma unroll
        for (int off = 16; off; off >>= 1) m = fmaxf(m, __shfl_xor_sync(0xffffffffu, m, off));
        float s = 0.f;
#pragma unroll
        for (int k = 0; k < 4; k++) s += __expf(v4[k] - m);
#pragma unroll
        for (int off = 16; off; off >>= 1) s += __shfl_xor_sync(0xffffffffu, s, off);
        if (lane == 0) { rmax[r] = m; rinv[r] = 1.f/s; }
    }
    for (int c = w; c < 128; c += 16) {
        float v4[4]; float m = -1e30f;
#pragma unroll
        for (int k = 0; k < 4; k++) { v4[k] = sS[(lane + 32*k)*129 + c]; m = fmaxf(m, v4[k]); }
#pragma unroll
        for (int off = 16; off; off >>= 1) m = fmaxf(m, __shfl_xor_sync(0xffffffffu, m, off));
        float s = 0.f;
#pragma unroll
        for (int k = 0; k < 4; k++) s += __expf(v4[k] - m);
#pragma unroll
        for (int off = 16; off; off >>= 1) s += __shfl_xor_sync(0xffffffffu, s, off);
        if (lane == 0) { cmax[c] = m; cinv[c] = 1.f/s; }
    }
    __syncthreads();

    // ---- phase 5: materialize M_rl (sM overlay) and M_lr^T (sS in place)
    for (int idx = tid; idx < 16384; idx += 512) {
        int u = idx >> 7, v = idx & 127;
        float raw = sS[u*129 + v];
        sM[u*129 + v] = __expf(raw - rmax[u]) * rinv[u];
        sS[u*129 + v] = __expf(raw - cmax[v]) * cinv[v];   // = M_lr[v][u]
    }
    __syncthreads();

    // ---- phase 6: validity maps
    if (tid < 128) {
        int u = tid; float accv = 0.f;
        for (int v = 0; v < 128; v++) {
            float A = 0.f;
#pragma unroll
            for (int d = -2; d <= 2; d++) {
                int uu = u + d;
                if ((unsigned)uu < 128u) A += sM[uu*129 + v];
            }
            accv += A * sS[u*129 + v];
        }
        sV[0][u] = tanhf(5.f * accv);
    } else if (tid < 256) {
        int u = tid - 128; float accv = 0.f;
        for (int v = 0; v < 128; v++) {
            float A = 0.f;
#pragma unroll
            for (int d = -2; d <= 2; d++) {
                int uu = u + d;
                if ((unsigned)uu < 128u) A += sS[v*129 + uu];
            }
            accv += A * sM[v*129 + u];
        }
        sV[1][u] = tanhf(5.f * accv);
    }
    __syncthreads();

    // ---- phase 7: transport GEMMs + blend
    {
        int half = w >> 3, c0 = (w & 7)*8;
        const float* X = half ? sXl : sXr;
        float acc[4][8];
#pragma unroll
        for (int i = 0; i < 4; i++)
#pragma unroll
            for (int j = 0; j < 8; j++) acc[i][j] = 0.f;

        for (int v = 0; v < 128; v++) {
            float a[4];
            if (half == 0) {
#pragma unroll
                for (int i = 0; i < 4; i++) a[i] = sM[(lane + 32*i)*129 + v];
            } else {
#pragma unroll
                for (int i = 0; i < 4; i++) a[i] = sS[v*129 + lane + 32*i];
            }
            const float4* xp = (const float4*)(X + v*68 + c0);
            float4 x0 = xp[0], x1 = xp[1];
            float bv[8] = {x0.x,x0.y,x0.z,x0.w, x1.x,x1.y,x1.z,x1.w};
#pragma unroll
            for (int i = 0; i < 4; i++)
#pragma unroll
                for (int j = 0; j < 8; j++)
                    acc[i][j] = fmaf(a[i], bv[j], acc[i][j]);
        }

        float* ob = out + (half ? (long)SZ : 0L) + b*CHW + h*Ww;
        const float* bb = (half ? xr : xl) + b*CHW + h*Ww;
#pragma unroll
        for (int i = 0; i < 4; i++) {
            int u = lane + 32*i;
            float Vv = sV[half][u];
#pragma unroll
            for (int j = 0; j < 8; j++) {
                int c = c0 + j;
                ob[c*HW + u] = fmaf(bb[c*HW + u], 1.f - Vv, acc[i][j]*Vv);
            }
        }
    }
}

// ---------------- launcher ----------------
extern "C" void kernel_launch(void* const* d_in, const int* in_sizes, int n_in,
                              void* d_out, int out_size) {
    const float* xl    = (const float*)d_in[0];
    const float* xr    = (const float*)d_in[1];
    const float* gamma = (const float*)d_in[2];
    const float* beta  = (const float*)d_in[3];
    const float* rw1   = (const float*)d_in[4];
    const float* rb1   = (const float*)d_in[5];
    const float* rw2   = (const float*)d_in[6];
    const float* rb2   = (const float*)d_in[7];
    const float* qw    = (const float*)d_in[8];
    const float* qb    = (const float*)d_in[9];
    const float* kw    = (const float*)d_in[10];
    const float* kb    = (const float*)d_in[11];
    float* out = (float*)d_out;

    const int CONV_SMEM = (CG*(TH+2)*130 + CG*CG*9) * 4;   // 92416

    cudaFuncSetAttribute(k_conv3<true>,  cudaFuncAttributeMaxDynamicSharedMemorySize, CONV_SMEM);
    cudaFuncSetAttribute(k_conv3<false>, cudaFuncAttributeMaxDynamicSharedMemorySize, CONV_SMEM);
    cudaFuncSetAttribute(k_attn,         cudaFuncAttributeMaxDynamicSharedMemorySize, ATT_SMEM);

    k_bnstats<<<dim3(Cc, 2), 256>>>(xl, xr, gamma, beta);
    k_conv3<true ><<<dim3(Hh/TH, Gg, 2*Bn), 256, CONV_SMEM>>>(xl, xr, rw1, rb1);
    k_conv3<false><<<dim3(Hh/TH, Gg, 2*Bn), 256, CONV_SMEM>>>(xl, xr, rw2, rb2);
    k_attn<<<NR, 512, ATT_SMEM>>>(xl, xr, qw, qb, kw, kb, out);
}

// round 3
// speedup vs baseline: 1.2214x; 1.0977x over previous
#include <cuda_runtime.h>
#include <math.h>

#define Bn 8
#define Cc 64
#define Hh 128
#define Ww 128
#define Gg 4
#define CG 16
#define HW (Hh*Ww)          // 16384
#define CHW (Cc*HW)         // 1048576
#define SZ (Bn*CHW)         // 8388608
#define NR (Bn*Hh)          // 1024
#define TH 8

typedef unsigned long long u64;

__device__ __forceinline__ u64 pk2(float lo, float hi) {
    u64 r;
    asm("mov.b64 %0, {%1, %2};" : "=l"(r)
        : "r"(__float_as_uint(lo)), "r"(__float_as_uint(hi)));
    return r;
}
__device__ __forceinline__ void upk2(u64 p, float& lo, float& hi) {
    unsigned a, bq;
    asm("mov.b64 {%0, %1}, %2;" : "=r"(a), "=r"(bq) : "l"(p));
    lo = __uint_as_float(a); hi = __uint_as_float(bq);
}
#define FMA2(d, a, b) asm("fma.rn.f32x2 %0, %1, %2, %3;" : "=l"(d) : "l"(a), "l"(b), "l"(d))

// scratch (device globals; no allocation allowed)
__device__ float g_t[2*SZ];        // conv1+lrelu outputs
__device__ float g_r[2*SZ];        // resblock outputs
__device__ float g_stats[2][2][Cc];// [side][a|d][c]: bn(x) = a*x + d

// ---------------- BN batch statistics ----------------
__global__ void __launch_bounds__(256) k_bnstats(const float* __restrict__ xl,
                                                 const float* __restrict__ xr,
                                                 const float* __restrict__ gamma,
                                                 const float* __restrict__ beta) {
    int c = blockIdx.x, side = blockIdx.y;
    const float* x = side ? xr : xl;
    int tid = threadIdx.x;
    double s = 0.0, s2 = 0.0;
    for (int b = 0; b < Bn; b++) {
        const float* p = x + b*CHW + c*HW;
        for (int i = tid; i < HW; i += 256) {
            float v = p[i];
            s += v; s2 += (double)v * v;
        }
    }
    __shared__ double sh[256], sh2[256];
    sh[tid] = s; sh2[tid] = s2;
    __syncthreads();
    for (int off = 128; off; off >>= 1) {
        if (tid < off) { sh[tid] += sh[tid+off]; sh2[tid] += sh2[tid+off]; }
        __syncthreads();
    }
    if (tid == 0) {
        double N = (double)(Bn*HW);
        double m = sh[0] / N;
        double var = sh2[0] / N - m*m;
        double rstd = 1.0 / sqrt(var + 1e-5);
        float a = gamma[c] * (float)rstd;
        float d = beta[c] - a * (float)m;
        g_stats[side][0][c] = a;
        g_stats[side][1][c] = d;
    }
}

// ---------------- grouped 3x3 conv (FFMA2) ----------------
// FIRST:  out = lrelu(conv3(bn(x)))            (bn applied during load)
// !FIRST: out = conv3(t) + bias + bn(x)        (residual fused in epilogue)
template<bool FIRST>
__global__ void __launch_bounds__(256) k_conv3(const float* __restrict__ xl,
                                               const float* __restrict__ xr,
                                               const float* __restrict__ wgt,
                                               const float* __restrict__ bias) {
    int ty = blockIdx.x, g = blockIdx.y;
    int side = blockIdx.z >> 3, b = blockIdx.z & 7;
    const float* xraw = side ? xr : xl;
    const float* in   = FIRST ? xraw : (g_t + side*SZ);
    float* out        = FIRST ? (g_t + side*SZ) : (g_r + side*SZ);

    extern __shared__ float sm[];
    float* sIn = sm;                 // [16][10][130] = 20800
    float* sW2 = sm + 20800;         // [ic][k][o] = 16*9*16 = 2304
    __shared__ float sa[CG], sd[CG];
    int tid = threadIdx.x;

    if (tid < CG) {
        sa[tid] = g_stats[side][0][g*CG + tid];
        sd[tid] = g_stats[side][1][g*CG + tid];
    }
    __syncthreads();

    // transposed weight load: sW2[(ic*9+k)*16 + o] = wgt[g][o][ic][k]
    for (int i = tid; i < 2304; i += 256) {
        int o = i & 15, rem = i >> 4;
        int k = rem % 9, ic = rem / 9;
        sW2[i] = wgt[g*2304 + (o*16 + ic)*9 + k];
    }

    int y0 = ty*TH - 1;
    const float* inb = in + b*CHW + g*CG*HW;
    for (int idx = tid; idx < CG*(TH+2)*130; idx += 256) {
        int ic  = idx / ((TH+2)*130);
        int rem = idx - ic*(TH+2)*130;
        int r   = rem / 130;
        int xx  = rem - r*130 - 1;
        int yy  = y0 + r;
        float v = 0.f;
        if ((unsigned)yy < (unsigned)Hh && (unsigned)xx < (unsigned)Ww) {
            v = inb[ic*HW + yy*Ww + xx];
            if (FIRST) v = fmaf(sa[ic], v, sd[ic]);
        }
        sIn[idx] = v;
    }
    __syncthreads();

    int xcol = tid & 127, half = tid >> 7;
    u64 acc2[4][TH];
#pragma unroll
    for (int o2 = 0; o2 < 4; o2++) {
        u64 bp = pk2(bias[g*CG + half*8 + 2*o2], bias[g*CG + half*8 + 2*o2 + 1]);
#pragma unroll
        for (int r = 0; r < TH; r++) acc2[o2][r] = bp;
    }

    for (int ic = 0; ic < CG; ic++) {
        const float* ip = sIn + ic*(TH+2)*130;
#pragma unroll
        for (int k = 0; k < 9; k++) {
            int dy = k / 3, dx = k - dy*3;
            const u64* wq = (const u64*)(sW2 + (ic*9 + k)*16 + half*8);
            u64 w0 = wq[0], w1 = wq[1], w2 = wq[2], w3 = wq[3];
#pragma unroll
            for (int r = 0; r < TH; r++) {
                float iv = ip[(r+dy)*130 + xcol + dx];
                u64 piv = pk2(iv, iv);
                FMA2(acc2[0][r], w0, piv);
                FMA2(acc2[1][r], w1, piv);
                FMA2(acc2[2][r], w2, piv);
                FMA2(acc2[3][r], w3, piv);
            }
        }
    }

    int ybase = ty*TH;
#pragma unroll
    for (int o2 = 0; o2 < 4; o2++) {
        int ocl0 = half*8 + 2*o2;
        int gbase = b*CHW + (g*CG + ocl0)*HW + ybase*Ww + xcol;
#pragma unroll
        for (int r = 0; r < TH; r++) {
            float v0, v1;
            upk2(acc2[o2][r], v0, v1);
            if (FIRST) {
                v0 = v0 > 0.f ? v0 : 0.1f*v0;
                v1 = v1 > 0.f ? v1 : 0.1f*v1;
            } else {
                v0 += fmaf(sa[ocl0],   xraw[gbase + r*Ww],      sd[ocl0]);
                v1 += fmaf(sa[ocl0+1], xraw[gbase + HW + r*Ww], sd[ocl0+1]);
            }
            out[gbase + r*Ww]      = v0;
            out[gbase + HW + r*Ww] = v1;
        }
    }
}

// ---------------- fused: QK 1x1 conv + score + dual softmax + validity + transport ----------------
// dynamic smem layout (floats):
//   sA  @0      : Q^T [128][65]     (8320)   \ overlaid later by sM [128][129]
//   sB  @8320   : K   [64][132]     (8448)   /
//   sS  @16768  : R rows -> scores -> M_lr^T [128][129] (16512)
//   sXl @33280  : x_left  rows [v][68] (8704)
//   sXr @41984  : x_right rows [v][68] (8704)
#define ATT_SMEM (50688*4)
__global__ void __launch_bounds__(512) k_attn(const float* __restrict__ xl,
                                              const float* __restrict__ xr,
                                              const float* __restrict__ qw, const float* __restrict__ qb,
                                              const float* __restrict__ kw, const float* __restrict__ kb,
                                              float* __restrict__ out) {
    int n = blockIdx.x, b = n >> 7, h = n & 127;
    extern __shared__ float sm[];
    float* sA  = sm;
    float* sB  = sm + 8320;
    float* sS  = sm + 16768;
    float* sXl = sm + 33280;
    float* sXr = sm + 41984;
    float* sM  = sm;                 // overlay (sA+sB dead after score GEMM)
    __shared__ float sWq[2048];      // transposed: [side][i][o]
    __shared__ float sBias[128];
    __shared__ float sMean[128];
    __shared__ float sV[2][128];
    __shared__ float sPart[512];
    int tid = threadIdx.x, lane = tid & 31, w = tid >> 5;

    // ---- phase 0: load resblock rows (into sS region), x rows, weights
    const float* Rl = g_r + b*CHW + h*Ww;
    const float* Rr = g_r + SZ + b*CHW + h*Ww;
    float* sRl = sS;          // [c][128]
    float* sRr = sS + 8192;
    for (int idx = tid; idx < 8192; idx += 512) {
        int c = idx >> 7, x = idx & 127;
        sRl[idx] = Rl[c*HW + x];
        sRr[idx] = Rr[c*HW + x];
        sXl[x*68 + c] = xl[b*CHW + c*HW + h*Ww + x];
        sXr[x*68 + c] = xr[b*CHW + c*HW + h*Ww + x];
    }
    // transposed 1x1 weights: sWq[side*1024 + i*64 + o]
    for (int idx = tid; idx < 2048; idx += 512) {
        int side = idx >> 10, rem = idx & 1023, i = rem >> 6, o = rem & 63;
        sWq[idx] = (side ? kw : qw)[o*16 + i];
    }
    if (tid < 64) { sBias[tid] = qb[tid]; sBias[64 + tid] = kb[tid]; }
    __syncthreads();

    // ---- phase 1: grouped 1x1 Q/K conv (FFMA2, 2 outputs/thread-task)
    for (int t = tid; t < 8192; t += 512) {
        int side = t >> 12, rem = t & 4095, o2 = rem >> 7, x = rem & 127;
        int o = o2*2, g = o >> 4;
        const float* R = side ? sRr : sRl;
        const u64* wp = (const u64*)(sWq + side*1024 + o);
        u64 acc = pk2(sBias[side*64 + o], sBias[side*64 + o + 1]);
#pragma unroll
        for (int i = 0; i < 16; i++) {
            float rv = R[(g*16 + i)*128 + x];
            u64 prv = pk2(rv, rv);
            FMA2(acc, wp[(unsigned)(i*32)], prv);
        }
        float a0, a1; upk2(acc, a0, a1);
        if (side == 0) { sA[x*65 + o] = a0; sA[x*65 + o + 1] = a1; }
        else           { sB[o*132 + x] = a0; sB[(o+1)*132 + x] = a1; }
    }
    __syncthreads();

    // ---- phase 2: per-channel row means, subtract
    for (int task = w; task < 128; task += 16) {
        float s = 0.f;
        if (task < 64) {
#pragma unroll
            for (int k = 0; k < 4; k++) s += sA[(lane + 32*k)*65 + task];
        } else {
#pragma unroll
            for (int k = 0; k < 4; k++) s += sB[(task - 64)*132 + lane + 32*k];
        }
#pragma unroll
        for (int off = 16; off; off >>= 1) s += __shfl_xor_sync(0xffffffffu, s, off);
        if (lane == 0) sMean[task] = s * (1.f/128.f);
    }
    __syncthreads();
    for (int idx = tid; idx < 8192; idx += 512) {
        int c = idx >> 7, u = idx & 127;
        sA[u*65 + c]  -= sMean[c];
        sB[c*132 + u] -= sMean[64 + c];
    }
    __syncthreads();

    // ---- phase 3: score GEMM S[u][v] = sum_c Q[c][u] K[c][v]  (FFMA2)
    {
        int rh = w >> 3, v0 = (w & 7)*16;
        int u0 = lane + 64*rh, u1 = u0 + 32;
        u64 acc2[2][8];
#pragma unroll
        for (int i = 0; i < 2; i++)
#pragma unroll
            for (int j = 0; j < 8; j++) acc2[i][j] = 0ull;
        for (int c = 0; c < 64; c++) {
            u64 pa0 = pk2(sA[u0*65 + c], sA[u0*65 + c]);
            u64 pa1 = pk2(sA[u1*65 + c], sA[u1*65 + c]);
            const u64* kp = (const u64*)(sB + c*132 + v0);
#pragma unroll
            for (int j = 0; j < 8; j++) {
                u64 bv = kp[j];
                FMA2(acc2[0][j], pa0, bv);
                FMA2(acc2[1][j], pa1, bv);
            }
        }
#pragma unroll
        for (int j = 0; j < 8; j++) {
            float l0, h0, l1, h1;
            upk2(acc2[0][j], l0, h0);
            upk2(acc2[1][j], l1, h1);
            sS[u0*129 + v0 + 2*j]     = l0;
            sS[u0*129 + v0 + 2*j + 1] = h0;
            sS[u1*129 + v0 + 2*j]     = l1;
            sS[u1*129 + v0 + 2*j + 1] = h1;
        }
    }
    __syncthreads();

    // ---- phase 4a: row softmax -> sM (reads sS, writes sM; one exp per element)
    for (int r = w; r < 128; r += 16) {
        float x4[4]; float m = -1e30f;
#pragma unroll
        for (int k = 0; k < 4; k++) { x4[k] = sS[r*129 + lane + 32*k]; m = fmaxf(m, x4[k]); }
#pragma unroll
        for (int off = 16; off; off >>= 1) m = fmaxf(m, __shfl_xor_sync(0xffffffffu, m, off));
        float e4[4]; float s = 0.f;
#pragma unroll
        for (int k = 0; k < 4; k++) { e4[k] = __expf(x4[k] - m); s += e4[k]; }
#pragma unroll
        for (int off = 16; off; off >>= 1) s += __shfl_xor_sync(0xffffffffu, s, off);
        float inv = 1.f / s;
#pragma unroll
        for (int k = 0; k < 4; k++) sM[r*129 + lane + 32*k] = e4[k] * inv;
    }
    __syncthreads();
    // ---- phase 4b: col softmax in place in sS (sS[u][v] <- M_lr[v][u])
    for (int c = w; c < 128; c += 16) {
        float x4[4]; float m = -1e30f;
#pragma unroll
        for (int k = 0; k < 4; k++) { x4[k] = sS[(lane + 32*k)*129 + c]; m = fmaxf(m, x4[k]); }
#pragma unroll
        for (int off = 16; off; off >>= 1) m = fmaxf(m, __shfl_xor_sync(0xffffffffu, m, off));
        float e4[4]; float s = 0.f;
#pragma unroll
        for (int k = 0; k < 4; k++) { e4[k] = __expf(x4[k] - m); s += e4[k]; }
#pragma unroll
        for (int off = 16; off; off >>= 1) s += __shfl_xor_sync(0xffffffffu, s, off);
        float inv = 1.f / s;
#pragma unroll
        for (int k = 0; k < 4; k++) sS[(lane + 32*k)*129 + c] = e4[k] * inv;
    }
    __syncthreads();

    // ---- phase 5: validity maps (all 512 threads: v-range split in two)
    {
        int task = tid & 255, vhalf = tid >> 8;
        int side = task >> 7, u = task & 127;
        int vA = vhalf*64, vB = vA + 64;
        float accv = 0.f;
        if (side == 0) {
            for (int v = vA; v < vB; v++) {
                float A = 0.f;
#pragma unroll
                for (int d = -2; d <= 2; d++) {
                    int uu = u + d;
                    if ((unsigned)uu < 128u) A += sM[uu*129 + v];
                }
                accv += A * sS[u*129 + v];
            }
        } else {
            for (int v = vA; v < vB; v++) {
                float A = 0.f;
#pragma unroll
                for (int d = -2; d <= 2; d++) {
                    int uu = u + d;
                    if ((unsigned)uu < 128u) A += sS[v*129 + uu];
                }
                accv += A * sM[v*129 + u];
            }
        }
        sPart[tid] = accv;
    }
    __syncthreads();
    if (tid < 256) {
        int side = tid >> 7, u = tid & 127;
        sV[side][u] = tanhf(5.f * (sPart[tid] + sPart[tid + 256]));
    }
    __syncthreads();

    // ---- phase 6: transport GEMMs + blend (FFMA2)
    {
        int half = w >> 3, c0 = (w & 7)*8;
        const float* X = half ? sXl : sXr;
        u64 acc2[4][4];
#pragma unroll
        for (int i = 0; i < 4; i++)
#pragma unroll
            for (int j = 0; j < 4; j++) acc2[i][j] = 0ull;

        for (int v = 0; v < 128; v++) {
            u64 pa[4];
            if (half == 0) {
#pragma unroll
                for (int i = 0; i < 4; i++) {
                    float a = sM[(lane + 32*i)*129 + v];
                    pa[i] = pk2(a, a);
                }
            } else {
#pragma unroll
                for (int i = 0; i < 4; i++) {
                    float a = sS[v*129 + lane + 32*i];
                    pa[i] = pk2(a, a);
                }
            }
            const u64* xp = (const u64*)(X + v*68 + c0);
            u64 b0 = xp[0], b1 = xp[1], b2 = xp[2], b3 = xp[3];
#pragma unroll
            for (int i = 0; i < 4; i++) {
                FMA2(acc2[i][0], pa[i], b0);
                FMA2(acc2[i][1], pa[i], b1);
                FMA2(acc2[i][2], pa[i], b2);
                FMA2(acc2[i][3], pa[i], b3);
            }
        }

        float* ob = out + (half ? (long)SZ : 0L) + b*CHW + h*Ww;
        const float* bb = (half ? xr : xl) + b*CHW + h*Ww;
#pragma unroll
        for (int i = 0; i < 4; i++) {
            int u = lane + 32*i;
            float Vv = sV[half][u];
#pragma unroll
            for (int j = 0; j < 4; j++) {
                float t0, t1;
                upk2(acc2[i][j], t0, t1);
                int c = c0 + 2*j;
                ob[c*HW + u]      = fmaf(bb[c*HW + u],      1.f - Vv, t0*Vv);
                ob[(c+1)*HW + u]  = fmaf(bb[(c+1)*HW + u],  1.f - Vv, t1*Vv);
            }
        }
    }
}

// ---------------- launcher ----------------
extern "C" void kernel_launch(void* const* d_in, const int* in_sizes, int n_in,
                              void* d_out, int out_size) {
    const float* xl    = (const float*)d_in[0];
    const float* xr    = (const float*)d_in[1];
    const float* gamma = (const float*)d_in[2];
    const float* beta  = (const float*)d_in[3];
    const float* rw1   = (const float*)d_in[4];
    const float* rb1   = (const float*)d_in[5];
    const float* rw2   = (const float*)d_in[6];
    const float* rb2   = (const float*)d_in[7];
    const float* qw    = (const float*)d_in[8];
    const float* qb    = (const float*)d_in[9];
    const float* kw    = (const float*)d_in[10];
    const float* kb    = (const float*)d_in[11];
    float* out = (float*)d_out;

    const int CONV_SMEM = (20800 + 2304) * 4;   // 92416

    cudaFuncSetAttribute(k_conv3<true>,  cudaFuncAttributeMaxDynamicSharedMemorySize, CONV_SMEM);
    cudaFuncSetAttribute(k_conv3<false>, cudaFuncAttributeMaxDynamicSharedMemorySize, CONV_SMEM);
    cudaFuncSetAttribute(k_attn,         cudaFuncAttributeMaxDynamicSharedMemorySize, ATT_SMEM);

    k_bnstats<<<dim3(Cc, 2), 256>>>(xl, xr, gamma, beta);
    k_conv3<true ><<<dim3(Hh/TH, Gg, 2*Bn), 256, CONV_SMEM>>>(xl, xr, rw1, rb1);
    k_conv3<false><<<dim3(Hh/TH, Gg, 2*Bn), 256, CONV_SMEM>>>(xl, xr, rw2, rb2);
    k_attn<<<NR, 512, ATT_SMEM>>>(xl, xr, qw, qb, kw, kb, out);
}

// round 4
// speedup vs baseline: 1.2255x; 1.0034x over previous
#include <cuda_runtime.h>
#include <math.h>

#define Bn 8
#define Cc 64
#define Hh 128
#define Ww 128
#define Gg 4
#define CG 16
#define HW (Hh*Ww)          // 16384
#define CHW (Cc*HW)         // 1048576
#define SZ (Bn*CHW)         // 8388608
#define NR (Bn*Hh)          // 1024
#define TH 4
#define SP 130              // sS/sM pitch (even -> 8B-aligned u64 rows)

typedef unsigned long long u64;

__device__ __forceinline__ u64 pk2(float lo, float hi) {
    u64 r;
    asm("mov.b64 %0, {%1, %2};" : "=l"(r)
        : "r"(__float_as_uint(lo)), "r"(__float_as_uint(hi)));
    return r;
}
__device__ __forceinline__ void upk2(u64 p, float& lo, float& hi) {
    unsigned a, bq;
    asm("mov.b64 {%0, %1}, %2;" : "=r"(a), "=r"(bq) : "l"(p));
    lo = __uint_as_float(a); hi = __uint_as_float(bq);
}
#define FMA2(d, a, b) asm("fma.rn.f32x2 %0, %1, %2, %3;" : "=l"(d) : "l"(a), "l"(b), "l"(d))

// scratch (device globals; no allocation allowed)
__device__ float g_t[2*SZ];        // conv1+lrelu outputs
__device__ float g_r[2*SZ];        // resblock outputs
__device__ float g_stats[2][2][Cc];// [side][a|d][c]: bn(x) = a*x + d

// ---------------- BN batch statistics ----------------
__global__ void __launch_bounds__(256) k_bnstats(const float* __restrict__ xl,
                                                 const float* __restrict__ xr,
                                                 const float* __restrict__ gamma,
                                                 const float* __restrict__ beta) {
    int c = blockIdx.x, side = blockIdx.y;
    const float* x = side ? xr : xl;
    int tid = threadIdx.x;
    float s = 0.f, s2 = 0.f;
    for (int b = 0; b < Bn; b++) {
        const float* p = x + b*CHW + c*HW;
        for (int i = tid; i < HW; i += 256) {
            float v = p[i];
            s += v; s2 = fmaf(v, v, s2);
        }
    }
    __shared__ float sh[256], sh2[256];
    sh[tid] = s; sh2[tid] = s2;
    __syncthreads();
    for (int off = 128; off; off >>= 1) {
        if (tid < off) { sh[tid] += sh[tid+off]; sh2[tid] += sh2[tid+off]; }
        __syncthreads();
    }
    if (tid == 0) {
        double N = (double)(Bn*HW);
        double m = (double)sh[0] / N;
        double var = (double)sh2[0] / N - m*m;
        double rstd = 1.0 / sqrt(var + 1e-5);
        float a = gamma[c] * (float)rstd;
        float d = beta[c] - a * (float)m;
        g_stats[side][0][c] = a;
        g_stats[side][1][c] = d;
    }
}

// ---------------- grouped 3x3 conv (FFMA2, TH=4 for 3 CTAs/SM) ----------------
template<bool FIRST>
__global__ void __launch_bounds__(256) k_conv3(const float* __restrict__ xl,
                                               const float* __restrict__ xr,
                                               const float* __restrict__ wgt,
                                               const float* __restrict__ bias) {
    int ty = blockIdx.x, g = blockIdx.y;
    int side = blockIdx.z >> 3, b = blockIdx.z & 7;
    const float* xraw = side ? xr : xl;
    const float* in   = FIRST ? xraw : (g_t + side*SZ);
    float* out        = FIRST ? (g_t + side*SZ) : (g_r + side*SZ);

    extern __shared__ float sm[];
    float* sIn = sm;                 // [16][6][130] = 12480
    float* sW2 = sm + 12480;         // [ic][k][o] = 16*9*16 = 2304
    __shared__ float sa[CG], sd[CG];
    int tid = threadIdx.x;

    if (tid < CG) {
        sa[tid] = g_stats[side][0][g*CG + tid];
        sd[tid] = g_stats[side][1][g*CG + tid];
    }
    __syncthreads();

    // transposed weight load: sW2[(ic*9+k)*16 + o] = wgt[g][o][ic][k]
    for (int i = tid; i < 2304; i += 256) {
        int o = i & 15, rem = i >> 4;
        int k = rem % 9, ic = rem / 9;
        sW2[i] = wgt[g*2304 + (o*16 + ic)*9 + k];
    }

    int y0 = ty*TH - 1;
    const float* inb = in + b*CHW + g*CG*HW;
    for (int idx = tid; idx < CG*(TH+2)*130; idx += 256) {
        int ic  = idx / ((TH+2)*130);
        int rem = idx - ic*(TH+2)*130;
        int r   = rem / 130;
        int xx  = rem - r*130 - 1;
        int yy  = y0 + r;
        float v = 0.f;
        if ((unsigned)yy < (unsigned)Hh && (unsigned)xx < (unsigned)Ww) {
            v = inb[ic*HW + yy*Ww + xx];
            if (FIRST) v = fmaf(sa[ic], v, sd[ic]);
        }
        sIn[idx] = v;
    }
    __syncthreads();

    int xcol = tid & 127, half = tid >> 7;
    u64 acc2[4][TH];
#pragma unroll
    for (int o2 = 0; o2 < 4; o2++) {
        u64 bp = pk2(bias[g*CG + half*8 + 2*o2], bias[g*CG + half*8 + 2*o2 + 1]);
#pragma unroll
        for (int r = 0; r < TH; r++) acc2[o2][r] = bp;
    }

    for (int ic = 0; ic < CG; ic++) {
        const float* ip = sIn + ic*(TH+2)*130;
#pragma unroll
        for (int k = 0; k < 9; k++) {
            int dy = k / 3, dx = k - dy*3;
            const u64* wq = (const u64*)(sW2 + (ic*9 + k)*16 + half*8);
            u64 w0 = wq[0], w1 = wq[1], w2 = wq[2], w3 = wq[3];
#pragma unroll
            for (int r = 0; r < TH; r++) {
                float iv = ip[(r+dy)*130 + xcol + dx];
                u64 piv = pk2(iv, iv);
                FMA2(acc2[0][r], w0, piv);
                FMA2(acc2[1][r], w1, piv);
                FMA2(acc2[2][r], w2, piv);
                FMA2(acc2[3][r], w3, piv);
            }
        }
    }

    int ybase = ty*TH;
#pragma unroll
    for (int o2 = 0; o2 < 4; o2++) {
        int ocl0 = half*8 + 2*o2;
        int gbase = b*CHW + (g*CG + ocl0)*HW + ybase*Ww + xcol;
#pragma unroll
        for (int r = 0; r < TH; r++) {
            float v0, v1;
            upk2(acc2[o2][r], v0, v1);
            if (FIRST) {
                v0 = v0 > 0.f ? v0 : 0.1f*v0;
                v1 = v1 > 0.f ? v1 : 0.1f*v1;
            } else {
                v0 += fmaf(sa[ocl0],   xraw[gbase + r*Ww],      sd[ocl0]);
                v1 += fmaf(sa[ocl0+1], xraw[gbase + HW + r*Ww], sd[ocl0+1]);
            }
            out[gbase + r*Ww]      = v0;
            out[gbase + HW + r*Ww] = v1;
        }
    }
}

// ---------------- fused: QK 1x1 conv + score + dual softmax + validity + transport ----------------
// dynamic smem (floats):
//   sA  @0      : Q^T [128][65]   \  overlaid by sM [128][130] after score GEMM
//   sB  @8320   : K   [64][132]   /
//   sS  @16768  : R rows -> scores -> M_lr^T [128][130]
//   sXl @33408  : x_left  rows [v][68]
//   sXr @42112  : x_right rows [v][68]
#define ATT_SMEM (50816*4)
__global__ void __launch_bounds__(512) k_attn(const float* __restrict__ xl,
                                              const float* __restrict__ xr,
                                              const float* __restrict__ qw, const float* __restrict__ qb,
                                              const float* __restrict__ kw, const float* __restrict__ kb,
                                              float* __restrict__ out) {
    int n = blockIdx.x, b = n >> 7, h = n & 127;
    extern __shared__ float sm[];
    float* sA  = sm;
    float* sB  = sm + 8320;
    float* sS  = sm + 16768;
    float* sXl = sm + 33408;
    float* sXr = sm + 42112;
    float* sM  = sm;                 // overlay (sA+sB dead after score GEMM)
    __shared__ float sWq[2048];      // transposed: [side][i][o]
    __shared__ float sBias[128];
    __shared__ float sMean[128];
    __shared__ float sV[2][128];
    __shared__ float sPart[512];
    int tid = threadIdx.x, lane = tid & 31, w = tid >> 5;

    // ---- phase 0: load resblock rows (into sS region), x rows, weights
    const float* Rl = g_r + b*CHW + h*Ww;
    const float* Rr = g_r + SZ + b*CHW + h*Ww;
    float* sRl = sS;          // [c][128]
    float* sRr = sS + 8192;
    for (int idx = tid; idx < 8192; idx += 512) {
        int c = idx >> 7, x = idx & 127;
        sRl[idx] = Rl[c*HW + x];
        sRr[idx] = Rr[c*HW + x];
        sXl[x*68 + c] = xl[b*CHW + c*HW + h*Ww + x];
        sXr[x*68 + c] = xr[b*CHW + c*HW + h*Ww + x];
    }
    for (int idx = tid; idx < 2048; idx += 512) {
        int side = idx >> 10, rem = idx & 1023, i = rem >> 6, o = rem & 63;
        sWq[idx] = (side ? kw : qw)[o*16 + i];
    }
    if (tid < 64) { sBias[tid] = qb[tid]; sBias[64 + tid] = kb[tid]; }
    __syncthreads();

    // ---- phase 1: grouped 1x1 Q/K conv (FFMA2)
    for (int t = tid; t < 8192; t += 512) {
        int side = t >> 12, rem = t & 4095, o2 = rem >> 7, x = rem & 127;
        int o = o2*2, g = o >> 4;
        const float* R = side ? sRr : sRl;
        const u64* wp = (const u64*)(sWq + side*1024 + o);
        u64 acc = pk2(sBias[side*64 + o], sBias[side*64 + o + 1]);
#pragma unroll
        for (int i = 0; i < 16; i++) {
            float rv = R[(g*16 + i)*128 + x];
            u64 prv = pk2(rv, rv);
            FMA2(acc, wp[(unsigned)(i*32)], prv);
        }
        float a0, a1; upk2(acc, a0, a1);
        if (side == 0) { sA[x*65 + o] = a0; sA[x*65 + o + 1] = a1; }
        else           { sB[o*132 + x] = a0; sB[(o+1)*132 + x] = a1; }
    }
    __syncthreads();

    // ---- phase 2: per-channel row means, subtract
    for (int task = w; task < 128; task += 16) {
        float s = 0.f;
        if (task < 64) {
#pragma unroll
            for (int k = 0; k < 4; k++) s += sA[(lane + 32*k)*65 + task];
        } else {
#pragma unroll
            for (int k = 0; k < 4; k++) s += sB[(task - 64)*132 + lane + 32*k];
        }
#pragma unroll
        for (int off = 16; off; off >>= 1) s += __shfl_xor_sync(0xffffffffu, s, off);
        if (lane == 0) sMean[task] = s * (1.f/128.f);
    }
    __syncthreads();
    for (int idx = tid; idx < 8192; idx += 512) {
        int c = idx >> 7, u = idx & 127;
        sA[u*65 + c]  -= sMean[c];
        sB[c*132 + u] -= sMean[64 + c];
    }
    __syncthreads();

    // ---- phase 3: score GEMM S[u][v] = sum_c Q[c][u] K[c][v]  (4u x 8v per thread)
    {
        int ub = w >> 1, vb = w & 1;
        int lu = lane >> 3, lv = lane & 7;
        int v0 = vb*64 + lv*8;
        int ubase = ub*16 + lu;
        u64 acc2[4][4];
#pragma unroll
        for (int i = 0; i < 4; i++)
#pragma unroll
            for (int j = 0; j < 4; j++) acc2[i][j] = 0ull;
        for (int c = 0; c < 64; c++) {
            u64 pa[4];
#pragma unroll
            for (int i = 0; i < 4; i++) {
                float a = sA[(ubase + 4*i)*65 + c];
                pa[i] = pk2(a, a);
            }
            const u64* kp = (const u64*)(sB + c*132 + v0);
            u64 b0 = kp[0], b1 = kp[1], b2 = kp[2], b3 = kp[3];
#pragma unroll
            for (int i = 0; i < 4; i++) {
                FMA2(acc2[i][0], pa[i], b0);
                FMA2(acc2[i][1], pa[i], b1);
                FMA2(acc2[i][2], pa[i], b2);
                FMA2(acc2[i][3], pa[i], b3);
            }
        }
#pragma unroll
        for (int i = 0; i < 4; i++) {
            u64* sp = (u64*)(sS + (ubase + 4*i)*SP + v0);
#pragma unroll
            for (int j = 0; j < 4; j++) sp[j] = acc2[i][j];
        }
    }
    __syncthreads();

    // ---- phase 4a: row softmax -> sM
    for (int r = w; r < 128; r += 16) {
        float x4[4]; float m = -1e30f;
#pragma unroll
        for (int k = 0; k < 4; k++) { x4[k] = sS[r*SP + lane + 32*k]; m = fmaxf(m, x4[k]); }
#pragma unroll
        for (int off = 16; off; off >>= 1) m = fmaxf(m, __shfl_xor_sync(0xffffffffu, m, off));
        float e4[4]; float s = 0.f;
#pragma unroll
        for (int k = 0; k < 4; k++) { e4[k] = __expf(x4[k] - m); s += e4[k]; }
#pragma unroll
        for (int off = 16; off; off >>= 1) s += __shfl_xor_sync(0xffffffffu, s, off);
        float inv = 1.f / s;
#pragma unroll
        for (int k = 0; k < 4; k++) sM[r*SP + lane + 32*k] = e4[k] * inv;
    }
    __syncthreads();
    // ---- phase 4b: col softmax in place in sS (sS[u][v] <- M_lr[v][u])
    for (int c = w; c < 128; c += 16) {
        float x4[4]; float m = -1e30f;
#pragma unroll
        for (int k = 0; k < 4; k++) { x4[k] = sS[(lane + 32*k)*SP + c]; m = fmaxf(m, x4[k]); }
#pragma unroll
        for (int off = 16; off; off >>= 1) m = fmaxf(m, __shfl_xor_sync(0xffffffffu, m, off));
        float e4[4]; float s = 0.f;
#pragma unroll
        for (int k = 0; k < 4; k++) { e4[k] = __expf(x4[k] - m); s += e4[k]; }
#pragma unroll
        for (int off = 16; off; off >>= 1) s += __shfl_xor_sync(0xffffffffu, s, off);
        float inv = 1.f / s;
#pragma unroll
        for (int k = 0; k < 4; k++) sS[(lane + 32*k)*SP + c] = e4[k] * inv;
    }
    __syncthreads();

    // ---- phase 5: validity maps (512 threads, v-range halved)
    {
        int task = tid & 255, vhalf = tid >> 8;
        int side = task >> 7, u = task & 127;
        int vA = vhalf*64, vB = vA + 64;
        float accv = 0.f;
        if (side == 0) {
            for (int v = vA; v < vB; v++) {
                float A = 0.f;
#pragma unroll
                for (int d = -2; d <= 2; d++) {
                    int uu = u + d;
                    if ((unsigned)uu < 128u) A += sM[uu*SP + v];
                }
                accv += A * sS[u*SP + v];
            }
        } else {
            for (int v = vA; v < vB; v++) {
                float A = 0.f;
#pragma unroll
                for (int d = -2; d <= 2; d++) {
                    int uu = u + d;
                    if ((unsigned)uu < 128u) A += sS[v*SP + uu];
                }
                accv += A * sM[v*SP + u];
            }
        }
        sPart[tid] = accv;
    }
    __syncthreads();
    if (tid < 256) {
        int side = tid >> 7, u = tid & 127;
        sV[side][u] = tanhf(5.f * (sPart[tid] + sPart[tid + 256]));
    }
    __syncthreads();

    // ---- phase 6: transport GEMMs + blend (4u x 8c per thread)
    {
        int side = w >> 3, ub = w & 7;
        int lu = lane >> 3, lc = lane & 7;
        int c0 = lc*8;
        int ubase = ub*16 + lu;
        const float* X = side ? sXl : sXr;
        u64 acc2[4][4];
#pragma unroll
        for (int i = 0; i < 4; i++)
#pragma unroll
            for (int j = 0; j < 4; j++) acc2[i][j] = 0ull;

        for (int v = 0; v < 128; v++) {
            u64 pa[4];
            if (side == 0) {
#pragma unroll
                for (int i = 0; i < 4; i++) {
                    float a = sM[(ubase + 4*i)*SP + v];
                    pa[i] = pk2(a, a);
                }
            } else {
#pragma unroll
                for (int i = 0; i < 4; i++) {
                    float a = sS[v*SP + ubase + 4*i];
                    pa[i] = pk2(a, a);
                }
            }
            const u64* xp = (const u64*)(X + v*68 + c0);
            u64 b0 = xp[0], b1 = xp[1], b2 = xp[2], b3 = xp[3];
#pragma unroll
            for (int i = 0; i < 4; i++) {
                FMA2(acc2[i][0], pa[i], b0);
                FMA2(acc2[i][1], pa[i], b1);
                FMA2(acc2[i][2], pa[i], b2);
                FMA2(acc2[i][3], pa[i], b3);
            }
        }

        float* ob = out + (side ? (long)SZ : 0L) + b*CHW + h*Ww;
        const float* bb = (side ? xr : xl) + b*CHW + h*Ww;
#pragma unroll
        for (int i = 0; i < 4; i++) {
            int u = ubase + 4*i;
            float Vv = sV[side][u];
#pragma unroll
            for (int j = 0; j < 4; j++) {
                float t0, t1;
                upk2(acc2[i][j], t0, t1);
                int c = c0 + 2*j;
                ob[c*HW + u]      = fmaf(bb[c*HW + u],      1.f - Vv, t0*Vv);
                ob[(c+1)*HW + u]  = fmaf(bb[(c+1)*HW + u],  1.f - Vv, t1*Vv);
            }
        }
    }
}

// ---------------- launcher ----------------
extern "C" void kernel_launch(void* const* d_in, const int* in_sizes, int n_in,
                              void* d_out, int out_size) {
    const float* xl    = (const float*)d_in[0];
    const float* xr    = (const float*)d_in[1];
    const float* gamma = (const float*)d_in[2];
    const float* beta  = (const float*)d_in[3];
    const float* rw1   = (const float*)d_in[4];
    const float* rb1   = (const float*)d_in[5];
    const float* rw2   = (const float*)d_in[6];
    const float* rb2   = (const float*)d_in[7];
    const float* qw    = (const float*)d_in[8];
    const float* qb    = (const float*)d_in[9];
    const float* kw    = (const float*)d_in[10];
    const float* kb    = (const float*)d_in[11];
    float* out = (float*)d_out;

    const int CONV_SMEM = (CG*(TH+2)*130 + 2304) * 4;   // 59136

    cudaFuncSetAttribute(k_conv3<true>,  cudaFuncAttributeMaxDynamicSharedMemorySize, CONV_SMEM);
    cudaFuncSetAttribute(k_conv3<false>, cudaFuncAttributeMaxDynamicSharedMemorySize, CONV_SMEM);
    cudaFuncSetAttribute(k_attn,         cudaFuncAttributeMaxDynamicSharedMemorySize, ATT_SMEM);

    k_bnstats<<<dim3(Cc, 2), 256>>>(xl, xr, gamma, beta);
    k_conv3<true ><<<dim3(Hh/TH, Gg, 2*Bn), 256, CONV_SMEM>>>(xl, xr, rw1, rb1);
    k_conv3<false><<<dim3(Hh/TH, Gg, 2*Bn), 256, CONV_SMEM>>>(xl, xr, rw2, rb2);
    k_attn<<<NR, 512, ATT_SMEM>>>(xl, xr, qw, qb, kw, kb, out);
}

// round 5
// speedup vs baseline: 1.4255x; 1.1632x over previous
#include <cuda_runtime.h>
#include <math.h>

#define Bn 8
#define Cc 64
#define Hh 128
#define Ww 128
#define Gg 4
#define CG 16
#define HW (Hh*Ww)          // 16384
#define CHW (Cc*HW)         // 1048576
#define SZ (Bn*CHW)         // 8388608
#define NR (Bn*Hh)          // 1024
#define TH 4
#define SP 129              // sS/sM pitch (odd -> conflict-free column walks)

typedef unsigned long long u64;

__device__ __forceinline__ u64 pk2(float lo, float hi) {
    u64 r;
    asm("mov.b64 %0, {%1, %2};" : "=l"(r)
        : "r"(__float_as_uint(lo)), "r"(__float_as_uint(hi)));
    return r;
}
__device__ __forceinline__ void upk2(u64 p, float& lo, float& hi) {
    unsigned a, bq;
    asm("mov.b64 {%0, %1}, %2;" : "=r"(a), "=r"(bq) : "l"(p));
    lo = __uint_as_float(a); hi = __uint_as_float(bq);
}
#define FMA2(d, a, b) asm("fma.rn.f32x2 %0, %1, %2, %3;" : "=l"(d) : "l"(a), "l"(b), "l"(d))

// scratch (device globals; no allocation allowed)
__device__ float g_t[2*SZ];        // conv1+lrelu outputs
__device__ float g_r[2*SZ];        // resblock outputs
__device__ float g_stats[2][2][Cc];// [side][a|d][c]: bn(x) = a*x + d

// ---------------- BN batch statistics ----------------
__global__ void __launch_bounds__(256) k_bnstats(const float* __restrict__ xl,
                                                 const float* __restrict__ xr,
                                                 const float* __restrict__ gamma,
                                                 const float* __restrict__ beta) {
    int c = blockIdx.x, side = blockIdx.y;
    const float* x = side ? xr : xl;
    int tid = threadIdx.x;
    float s = 0.f, s2 = 0.f;
    for (int b = 0; b < Bn; b++) {
        const float* p = x + b*CHW + c*HW;
        for (int i = tid; i < HW; i += 256) {
            float v = p[i];
            s += v; s2 = fmaf(v, v, s2);
        }
    }
    __shared__ float sh[256], sh2[256];
    sh[tid] = s; sh2[tid] = s2;
    __syncthreads();
    for (int off = 128; off; off >>= 1) {
        if (tid < off) { sh[tid] += sh[tid+off]; sh2[tid] += sh2[tid+off]; }
        __syncthreads();
    }
    if (tid == 0) {
        double N = (double)(Bn*HW);
        double m = (double)sh[0] / N;
        double var = (double)sh2[0] / N - m*m;
        double rstd = 1.0 / sqrt(var + 1e-5);
        float a = gamma[c] * (float)rstd;
        float d = beta[c] - a * (float)m;
        g_stats[side][0][c] = a;
        g_stats[side][1][c] = d;
    }
}

// ---------------- grouped 3x3 conv (FFMA2, TH=4 for 3 CTAs/SM) ----------------
template<bool FIRST>
__global__ void __launch_bounds__(256) k_conv3(const float* __restrict__ xl,
                                               const float* __restrict__ xr,
                                               const float* __restrict__ wgt,
                                               const float* __restrict__ bias) {
    int ty = blockIdx.x, g = blockIdx.y;
    int side = blockIdx.z >> 3, b = blockIdx.z & 7;
    const float* xraw = side ? xr : xl;
    const float* in   = FIRST ? xraw : (g_t + side*SZ);
    float* out        = FIRST ? (g_t + side*SZ) : (g_r + side*SZ);

    extern __shared__ float sm[];
    float* sIn = sm;                 // [16][6][130] = 12480
    float* sW2 = sm + 12480;         // [ic][k][o] = 16*9*16 = 2304
    __shared__ float sa[CG], sd[CG];
    int tid = threadIdx.x;

    if (tid < CG) {
        sa[tid] = g_stats[side][0][g*CG + tid];
        sd[tid] = g_stats[side][1][g*CG + tid];
    }
    __syncthreads();

    // transposed weight load: sW2[(ic*9+k)*16 + o] = wgt[g][o][ic][k]
    for (int i = tid; i < 2304; i += 256) {
        int o = i & 15, rem = i >> 4;
        int k = rem % 9, ic = rem / 9;
        sW2[i] = wgt[g*2304 + (o*16 + ic)*9 + k];
    }

    int y0 = ty*TH - 1;
    const float* inb = in + b*CHW + g*CG*HW;
    for (int idx = tid; idx < CG*(TH+2)*130; idx += 256) {
        int ic  = idx / ((TH+2)*130);
        int rem = idx - ic*(TH+2)*130;
        int r   = rem / 130;
        int xx  = rem - r*130 - 1;
        int yy  = y0 + r;
        float v = 0.f;
        if ((unsigned)yy < (unsigned)Hh && (unsigned)xx < (unsigned)Ww) {
            v = inb[ic*HW + yy*Ww + xx];
            if (FIRST) v = fmaf(sa[ic], v, sd[ic]);
        }
        sIn[idx] = v;
    }
    __syncthreads();

    int xcol = tid & 127, half = tid >> 7;
    u64 acc2[4][TH];
#pragma unroll
    for (int o2 = 0; o2 < 4; o2++) {
        u64 bp = pk2(bias[g*CG + half*8 + 2*o2], bias[g*CG + half*8 + 2*o2 + 1]);
#pragma unroll
        for (int r = 0; r < TH; r++) acc2[o2][r] = bp;
    }

    for (int ic = 0; ic < CG; ic++) {
        const float* ip = sIn + ic*(TH+2)*130;
#pragma unroll
        for (int k = 0; k < 9; k++) {
            int dy = k / 3, dx = k - dy*3;
            const ulonglong2* wq = (const ulonglong2*)(sW2 + (ic*9 + k)*16 + half*8);
            ulonglong2 wA = wq[0], wB = wq[1];
#pragma unroll
            for (int r = 0; r < TH; r++) {
                float iv = ip[(r+dy)*130 + xcol + dx];
                u64 piv = pk2(iv, iv);
                FMA2(acc2[0][r], wA.x, piv);
                FMA2(acc2[1][r], wA.y, piv);
                FMA2(acc2[2][r], wB.x, piv);
                FMA2(acc2[3][r], wB.y, piv);
            }
        }
    }

    int ybase = ty*TH;
#pragma unroll
    for (int o2 = 0; o2 < 4; o2++) {
        int ocl0 = half*8 + 2*o2;
        int gbase = b*CHW + (g*CG + ocl0)*HW + ybase*Ww + xcol;
#pragma unroll
        for (int r = 0; r < TH; r++) {
            float v0, v1;
            upk2(acc2[o2][r], v0, v1);
            if (FIRST) {
                v0 = v0 > 0.f ? v0 : 0.1f*v0;
                v1 = v1 > 0.f ? v1 : 0.1f*v1;
            } else {
                v0 += fmaf(sa[ocl0],   xraw[gbase + r*Ww],      sd[ocl0]);
                v1 += fmaf(sa[ocl0+1], xraw[gbase + HW + r*Ww], sd[ocl0+1]);
            }
            out[gbase + r*Ww]      = v0;
            out[gbase + HW + r*Ww] = v1;
        }
    }
}

// ---------------- fused: QK 1x1 conv + score + dual softmax + validity + transport ----------------
// dynamic smem (floats):
//   sA  @0      : Q^T [128][65]   \  overlaid by sM [128][129] after score GEMM
//   sB  @8320   : K   [64][132]   /
//   sS  @16768  : R rows -> scores -> M_lr^T [128][129]
//   sXl @33280  : x_left  rows [v][68]
//   sXr @41984  : x_right rows [v][68]
#define ATT_SMEM (50688*4)
__global__ void __launch_bounds__(512) k_attn(const float* __restrict__ xl,
                                              const float* __restrict__ xr,
                                              const float* __restrict__ qw, const float* __restrict__ qb,
                                              const float* __restrict__ kw, const float* __restrict__ kb,
                                              float* __restrict__ out) {
    int n = blockIdx.x, b = n >> 7, h = n & 127;
    extern __shared__ float sm[];
    float* sA  = sm;
    float* sB  = sm + 8320;
    float* sS  = sm + 16768;
    float* sXl = sm + 33280;
    float* sXr = sm + 41984;
    float* sM  = sm;                 // overlay (sA+sB dead after score GEMM)
    __shared__ float sWq[2048];      // transposed: [side][i][o]
    __shared__ float sBias[128];
    __shared__ float sMean[128];
    __shared__ float sV[2][128];
    __shared__ float sPart[512];
    int tid = threadIdx.x, lane = tid & 31, w = tid >> 5;

    // ---- phase 0: load resblock rows (into sS region), x rows, weights
    const float* Rl = g_r + b*CHW + h*Ww;
    const float* Rr = g_r + SZ + b*CHW + h*Ww;
    float* sRl = sS;          // [c][128]
    float* sRr = sS + 8192;
    for (int idx = tid; idx < 8192; idx += 512) {
        int c = idx >> 7, x = idx & 127;
        sRl[idx] = Rl[c*HW + x];
        sRr[idx] = Rr[c*HW + x];
        sXl[x*68 + c] = xl[b*CHW + c*HW + h*Ww + x];
        sXr[x*68 + c] = xr[b*CHW + c*HW + h*Ww + x];
    }
    for (int idx = tid; idx < 2048; idx += 512) {
        int side = idx >> 10, rem = idx & 1023, i = rem >> 6, o = rem & 63;
        sWq[idx] = (side ? kw : qw)[o*16 + i];
    }
    if (tid < 64) { sBias[tid] = qb[tid]; sBias[64 + tid] = kb[tid]; }
    __syncthreads();

    // ---- phase 1: grouped 1x1 Q/K conv (FFMA2)
    for (int t = tid; t < 8192; t += 512) {
        int side = t >> 12, rem = t & 4095, o2 = rem >> 7, x = rem & 127;
        int o = o2*2, g = o >> 4;
        const float* R = side ? sRr : sRl;
        const u64* wp = (const u64*)(sWq + side*1024 + o);
        u64 acc = pk2(sBias[side*64 + o], sBias[side*64 + o + 1]);
#pragma unroll
        for (int i = 0; i < 16; i++) {
            float rv = R[(g*16 + i)*128 + x];
            u64 prv = pk2(rv, rv);
            FMA2(acc, wp[(unsigned)(i*32)], prv);
        }
        float a0, a1; upk2(acc, a0, a1);
        if (side == 0) { sA[x*65 + o] = a0; sA[x*65 + o + 1] = a1; }
        else           { sB[o*132 + x] = a0; sB[(o+1)*132 + x] = a1; }
    }
    __syncthreads();

    // ---- phase 2: per-channel row means, subtract
    for (int task = w; task < 128; task += 16) {
        float s = 0.f;
        if (task < 64) {
#pragma unroll
            for (int k = 0; k < 4; k++) s += sA[(lane + 32*k)*65 + task];
        } else {
#pragma unroll
            for (int k = 0; k < 4; k++) s += sB[(task - 64)*132 + lane + 32*k];
        }
#pragma unroll
        for (int off = 16; off; off >>= 1) s += __shfl_xor_sync(0xffffffffu, s, off);
        if (lane == 0) sMean[task] = s * (1.f/128.f);
    }
    __syncthreads();
    for (int idx = tid; idx < 8192; idx += 512) {
        int c = idx >> 7, u = idx & 127;
        sA[u*65 + c]  -= sMean[c];
        sB[c*132 + u] -= sMean[64 + c];
    }
    __syncthreads();

    // ---- phase 3: score GEMM S[u][v] = sum_c Q[c][u] K[c][v]  (2u x 16v, b broadcast)
    {
        int rh = w >> 3, v0 = (w & 7)*16;
        int u0 = lane + 64*rh, u1 = u0 + 32;
        u64 acc2[2][8];
#pragma unroll
        for (int i = 0; i < 2; i++)
#pragma unroll
            for (int j = 0; j < 8; j++) acc2[i][j] = 0ull;
        for (int c = 0; c < 64; c++) {
            float a0 = sA[u0*65 + c];
            float a1 = sA[u1*65 + c];
            u64 pa0 = pk2(a0, a0);
            u64 pa1 = pk2(a1, a1);
            const ulonglong2* kp = (const ulonglong2*)(sB + c*132 + v0);
            ulonglong2 q0 = kp[0], q1 = kp[1], q2 = kp[2], q3 = kp[3];
            u64 bv[8] = {q0.x, q0.y, q1.x, q1.y, q2.x, q2.y, q3.x, q3.y};
#pragma unroll
            for (int j = 0; j < 8; j++) {
                FMA2(acc2[0][j], pa0, bv[j]);
                FMA2(acc2[1][j], pa1, bv[j]);
            }
        }
#pragma unroll
        for (int j = 0; j < 8; j++) {
            float l0, h0, l1, h1;
            upk2(acc2[0][j], l0, h0);
            upk2(acc2[1][j], l1, h1);
            sS[u0*SP + v0 + 2*j]     = l0;
            sS[u0*SP + v0 + 2*j + 1] = h0;
            sS[u1*SP + v0 + 2*j]     = l1;
            sS[u1*SP + v0 + 2*j + 1] = h1;
        }
    }
    __syncthreads();

    // ---- phase 4a: row softmax -> sM
    for (int r = w; r < 128; r += 16) {
        float x4[4]; float m = -1e30f;
#pragma unroll
        for (int k = 0; k < 4; k++) { x4[k] = sS[r*SP + lane + 32*k]; m = fmaxf(m, x4[k]); }
#pragma unroll
        for (int off = 16; off; off >>= 1) m = fmaxf(m, __shfl_xor_sync(0xffffffffu, m, off));
        float e4[4]; float s = 0.f;
#pragma unroll
        for (int k = 0; k < 4; k++) { e4[k] = __expf(x4[k] - m); s += e4[k]; }
#pragma unroll
        for (int off = 16; off; off >>= 1) s += __shfl_xor_sync(0xffffffffu, s, off);
        float inv = 1.f / s;
#pragma unroll
        for (int k = 0; k < 4; k++) sM[r*SP + lane + 32*k] = e4[k] * inv;
    }
    __syncthreads();
    // ---- phase 4b: col softmax in place in sS (sS[u][v] <- M_lr[v][u])
    for (int c = w; c < 128; c += 16) {
        float x4[4]; float m = -1e30f;
#pragma unroll
        for (int k = 0; k < 4; k++) { x4[k] = sS[(lane + 32*k)*SP + c]; m = fmaxf(m, x4[k]); }
#pragma unroll
        for (int off = 16; off; off >>= 1) m = fmaxf(m, __shfl_xor_sync(0xffffffffu, m, off));
        float e4[4]; float s = 0.f;
#pragma unroll
        for (int k = 0; k < 4; k++) { e4[k] = __expf(x4[k] - m); s += e4[k]; }
#pragma unroll
        for (int off = 16; off; off >>= 1) s += __shfl_xor_sync(0xffffffffu, s, off);
        float inv = 1.f / s;
#pragma unroll
        for (int k = 0; k < 4; k++) sS[(lane + 32*k)*SP + c] = e4[k] * inv;
    }
    __syncthreads();

    // ---- phase 5: validity maps (512 threads, v-range halved)
    {
        int task = tid & 255, vhalf = tid >> 8;
        int side = task >> 7, u = task & 127;
        int vA = vhalf*64, vB = vA + 64;
        float accv = 0.f;
        if (side == 0) {
            for (int v = vA; v < vB; v++) {
                float A = 0.f;
#pragma unroll
                for (int d = -2; d <= 2; d++) {
                    int uu = u + d;
                    if ((unsigned)uu < 128u) A += sM[uu*SP + v];
                }
                accv += A * sS[u*SP + v];
            }
        } else {
            for (int v = vA; v < vB; v++) {
                float A = 0.f;
#pragma unroll
                for (int d = -2; d <= 2; d++) {
                    int uu = u + d;
                    if ((unsigned)uu < 128u) A += sS[v*SP + uu];
                }
                accv += A * sM[v*SP + u];
            }
        }
        sPart[tid] = accv;
    }
    __syncthreads();
    if (tid < 256) {
        int side = tid >> 7, u = tid & 127;
        sV[side][u] = tanhf(5.f * (sPart[tid] + sPart[tid + 256]));
    }
    __syncthreads();

    // ---- phase 6: transport GEMMs + blend (4u x 8c, X broadcast)
    {
        int half = w >> 3, c0 = (w & 7)*8;
        const float* X = half ? sXl : sXr;
        u64 acc2[4][4];
#pragma unroll
        for (int i = 0; i < 4; i++)
#pragma unroll
            for (int j = 0; j < 4; j++) acc2[i][j] = 0ull;

        for (int v = 0; v < 128; v++) {
            u64 pa[4];
            if (half == 0) {
#pragma unroll
                for (int i = 0; i < 4; i++) {
                    float a = sM[(lane + 32*i)*SP + v];
                    pa[i] = pk2(a, a);
                }
            } else {
#pragma unroll
                for (int i = 0; i < 4; i++) {
                    float a = sS[v*SP + lane + 32*i];
                    pa[i] = pk2(a, a);
                }
            }
            const ulonglong2* xp = (const ulonglong2*)(X + v*68 + c0);
            ulonglong2 xA = xp[0], xB = xp[1];
#pragma unroll
            for (int i = 0; i < 4; i++) {
                FMA2(acc2[i][0], pa[i], xA.x);
                FMA2(acc2[i][1], pa[i], xA.y);
                FMA2(acc2[i][2], pa[i], xB.x);
                FMA2(acc2[i][3], pa[i], xB.y);
            }
        }

        float* ob = out + (half ? (long)SZ : 0L) + b*CHW + h*Ww;
        const float* bb = (half ? xr : xl) + b*CHW + h*Ww;
#pragma unroll
        for (int i = 0; i < 4; i++) {
            int u = lane + 32*i;
            float Vv = sV[half][u];
#pragma unroll
            for (int j = 0; j < 4; j++) {
                float t0, t1;
                upk2(acc2[i][j], t0, t1);
                int c = c0 + 2*j;
                ob[c*HW + u]      = fmaf(bb[c*HW + u],      1.f - Vv, t0*Vv);
                ob[(c+1)*HW + u]  = fmaf(bb[(c+1)*HW + u],  1.f - Vv, t1*Vv);
            }
        }
    }
}

// ---------------- launcher ----------------
extern "C" void kernel_launch(void* const* d_in, const int* in_sizes, int n_in,
                              void* d_out, int out_size) {
    const float* xl    = (const float*)d_in[0];
    const float* xr    = (const float*)d_in[1];
    const float* gamma = (const float*)d_in[2];
    const float* beta  = (const float*)d_in[3];
    const float* rw1   = (const float*)d_in[4];
    const float* rb1   = (const float*)d_in[5];
    const float* rw2   = (const float*)d_in[6];
    const float* rb2   = (const float*)d_in[7];
    const float* qw    = (const float*)d_in[8];
    const float* qb    = (const float*)d_in[9];
    const float* kw    = (const float*)d_in[10];
    const float* kb    = (const float*)d_in[11];
    float* out = (float*)d_out;

    const int CONV_SMEM = (CG*(TH+2)*130 + 2304) * 4;   // 59136

    cudaFuncSetAttribute(k_conv3<true>,  cudaFuncAttributeMaxDynamicSharedMemorySize, CONV_SMEM);
    cudaFuncSetAttribute(k_conv3<false>, cudaFuncAttributeMaxDynamicSharedMemorySize, CONV_SMEM);
    cudaFuncSetAttribute(k_attn,         cudaFuncAttributeMaxDynamicSharedMemorySize, ATT_SMEM);

    k_bnstats<<<dim3(Cc, 2), 256>>>(xl, xr, gamma, beta);
    k_conv3<true ><<<dim3(Hh/TH, Gg, 2*Bn), 256, CONV_SMEM>>>(xl, xr, rw1, rb1);
    k_conv3<false><<<dim3(Hh/TH, Gg, 2*Bn), 256, CONV_SMEM>>>(xl, xr, rw2, rb2);
    k_attn<<<NR, 512, ATT_SMEM>>>(xl, xr, qw, qb, kw, kb, out);
}

// round 7
// speedup vs baseline: 1.4317x; 1.0043x over previous
#include <cuda_runtime.h>
#include <math.h>

#define Bn 8
#define Cc 64
#define Hh 128
#define Ww 128
#define Gg 4
#define CG 16
#define HW (Hh*Ww)          // 16384
#define CHW (Cc*HW)         // 1048576
#define SZ (Bn*CHW)         // 8388608
#define NR (Bn*Hh)          // 1024
#define TH 4
#define SP 129              // sS/sM pitch (odd -> conflict-free column walks)

typedef unsigned long long u64;

__device__ __forceinline__ u64 pk2(float lo, float hi) {
    u64 r;
    asm("mov.b64 %0, {%1, %2};" : "=l"(r)
        : "r"(__float_as_uint(lo)), "r"(__float_as_uint(hi)));
    return r;
}
__device__ __forceinline__ void upk2(u64 p, float& lo, float& hi) {
    unsigned a, bq;
    asm("mov.b64 {%0, %1}, %2;" : "=r"(a), "=r"(bq) : "l"(p));
    lo = __uint_as_float(a); hi = __uint_as_float(bq);
}
#define FMA2(d, a, b) asm("fma.rn.f32x2 %0, %1, %2, %3;" : "=l"(d) : "l"(a), "l"(b), "l"(d))

// scratch (device globals; no allocation allowed)
__device__ float g_t[2*SZ];        // conv1+lrelu outputs
__device__ float g_r[2*SZ];        // resblock outputs
__device__ float g_stats[2][2][Cc];// [side][a|d][c]: bn(x) = a*x + d

// ---------------- BN batch statistics ----------------
__global__ void __launch_bounds__(256) k_bnstats(const float* __restrict__ xl,
                                                 const float* __restrict__ xr,
                                                 const float* __restrict__ gamma,
                                                 const float* __restrict__ beta) {
    int c = blockIdx.x, side = blockIdx.y;
    const float* x = side ? xr : xl;
    int tid = threadIdx.x;
    float s = 0.f, s2 = 0.f;
    for (int b = 0; b < Bn; b++) {
        const float* p = x + b*CHW + c*HW;
        for (int i = tid; i < HW; i += 256) {
            float v = p[i];
            s += v; s2 = fmaf(v, v, s2);
        }
    }
    __shared__ float sh[256], sh2[256];
    sh[tid] = s; sh2[tid] = s2;
    __syncthreads();
    for (int off = 128; off; off >>= 1) {
        if (tid < off) { sh[tid] += sh[tid+off]; sh2[tid] += sh2[tid+off]; }
        __syncthreads();
    }
    if (tid == 0) {
        double N = (double)(Bn*HW);
        double m = (double)sh[0] / N;
        double var = (double)sh2[0] / N - m*m;
        double rstd = 1.0 / sqrt(var + 1e-5);
        float a = gamma[c] * (float)rstd;
        float d = beta[c] - a * (float)m;
        g_stats[side][0][c] = a;
        g_stats[side][1][c] = d;
    }
}

// ---------------- grouped 3x3 conv (FFMA2, TH=4 for 3 CTAs/SM) ----------------
template<bool FIRST>
__global__ void __launch_bounds__(256) k_conv3(const float* __restrict__ xl,
                                               const float* __restrict__ xr,
                                               const float* __restrict__ wgt,
                                               const float* __restrict__ bias) {
    int ty = blockIdx.x, g = blockIdx.y;
    int side = blockIdx.z >> 3, b = blockIdx.z & 7;
    const float* xraw = side ? xr : xl;
    const float* in   = FIRST ? xraw : (g_t + side*SZ);
    float* out        = FIRST ? (g_t + side*SZ) : (g_r + side*SZ);

    extern __shared__ float sm[];
    float* sIn = sm;                 // [16][6][130] = 12480
    float* sW2 = sm + 12480;         // [ic][k][o] = 16*9*16 = 2304
    __shared__ float sa[CG], sd[CG];
    int tid = threadIdx.x;

    if (tid < CG) {
        sa[tid] = g_stats[side][0][g*CG + tid];
        sd[tid] = g_stats[side][1][g*CG + tid];
    }
    __syncthreads();

    // transposed weight load: sW2[(ic*9+k)*16 + o] = wgt[g][o][ic][k]
    for (int i = tid; i < 2304; i += 256) {
        int o = i & 15, rem = i >> 4;
        int k = rem % 9, ic = rem / 9;
        sW2[i] = wgt[g*2304 + (o*16 + ic)*9 + k];
    }

    int y0 = ty*TH - 1;
    const float* inb = in + b*CHW + g*CG*HW;
    for (int idx = tid; idx < CG*(TH+2)*130; idx += 256) {
        int ic  = idx / ((TH+2)*130);
        int rem = idx - ic*(TH+2)*130;
        int r   = rem / 130;
        int xx  = rem - r*130 - 1;
        int yy  = y0 + r;
        float v = 0.f;
        if ((unsigned)yy < (unsigned)Hh && (unsigned)xx < (unsigned)Ww) {
            v = inb[ic*HW + yy*Ww + xx];
            if (FIRST) v = fmaf(sa[ic], v, sd[ic]);
        }
        sIn[idx] = v;
    }
    __syncthreads();

    int xcol = tid & 127, half = tid >> 7;
    u64 acc2[4][TH];
#pragma unroll
    for (int o2 = 0; o2 < 4; o2++) {
        u64 bp = pk2(bias[g*CG + half*8 + 2*o2], bias[g*CG + half*8 + 2*o2 + 1]);
#pragma unroll
        for (int r = 0; r < TH; r++) acc2[o2][r] = bp;
    }

    for (int ic = 0; ic < CG; ic++) {
        const float* ip = sIn + ic*(TH+2)*130;
#pragma unroll
        for (int k = 0; k < 9; k++) {
            int dy = k / 3, dx = k - dy*3;
            const ulonglong2* wq = (const ulonglong2*)(sW2 + (ic*9 + k)*16 + half*8);
            ulonglong2 wA = wq[0], wB = wq[1];
#pragma unroll
            for (int r = 0; r < TH; r++) {
                float iv = ip[(r+dy)*130 + xcol + dx];
                u64 piv = pk2(iv, iv);
                FMA2(acc2[0][r], wA.x, piv);
                FMA2(acc2[1][r], wA.y, piv);
                FMA2(acc2[2][r], wB.x, piv);
                FMA2(acc2[3][r], wB.y, piv);
            }
        }
    }

    int ybase = ty*TH;
#pragma unroll
    for (int o2 = 0; o2 < 4; o2++) {
        int ocl0 = half*8 + 2*o2;
        int gbase = b*CHW + (g*CG + ocl0)*HW + ybase*Ww + xcol;
#pragma unroll
        for (int r = 0; r < TH; r++) {
            float v0, v1;
            upk2(acc2[o2][r], v0, v1);
            if (FIRST) {
                v0 = v0 > 0.f ? v0 : 0.1f*v0;
                v1 = v1 > 0.f ? v1 : 0.1f*v1;
            } else {
                v0 += fmaf(sa[ocl0],   xraw[gbase + r*Ww],      sd[ocl0]);
                v1 += fmaf(sa[ocl0+1], xraw[gbase + HW + r*Ww], sd[ocl0+1]);
            }
            out[gbase + r*Ww]      = v0;
            out[gbase + HW + r*Ww] = v1;
        }
    }
}

// ---------------- fused: QK 1x1 conv + score + dual softmax + validity + transport ----------------
// 1024 threads (32 warps) for latency hiding; same smem footprint.
// dynamic smem (floats):
//   sA  @0      : Q^T [128][65]   \  overlaid by sM [128][129] after score GEMM
//   sB  @8320   : K   [64][132]   /
//   sS  @16768  : R rows -> scores -> M_lr^T [128][129]
//   sXl @33280  : x_left  rows [v][68]
//   sXr @41984  : x_right rows [v][68]
#define ATT_SMEM (50688*4)
#define NT 1024
__global__ void __launch_bounds__(NT) k_attn(const float* __restrict__ xl,
                                             const float* __restrict__ xr,
                                             const float* __restrict__ qw, const float* __restrict__ qb,
                                             const float* __restrict__ kw, const float* __restrict__ kb,
                                             float* __restrict__ out) {
    int n = blockIdx.x, b = n >> 7, h = n & 127;
    extern __shared__ float sm[];
    float* sA  = sm;
    float* sB  = sm + 8320;
    float* sS  = sm + 16768;
    float* sXl = sm + 33280;
    float* sXr = sm + 41984;
    float* sM  = sm;                 // overlay (sA+sB dead after score GEMM)
    __shared__ float sWq[2048];      // transposed: [side][i][o]
    __shared__ float sBias[128];
    __shared__ float sMean[128];
    __shared__ float sV[2][128];
    __shared__ float sPart[NT];
    int tid = threadIdx.x, lane = tid & 31, w = tid >> 5;

    // ---- phase 0: load resblock rows (into sS region), x rows, weights
    const float* Rl = g_r + b*CHW + h*Ww;
    const float* Rr = g_r + SZ + b*CHW + h*Ww;
    float* sRl = sS;          // [c][128]
    float* sRr = sS + 8192;
    for (int idx = tid; idx < 8192; idx += NT) {
        int c = idx >> 7, x = idx & 127;
        sRl[idx] = Rl[c*HW + x];
        sRr[idx] = Rr[c*HW + x];
        sXl[x*68 + c] = xl[b*CHW + c*HW + h*Ww + x];
        sXr[x*68 + c] = xr[b*CHW + c*HW + h*Ww + x];
    }
    for (int idx = tid; idx < 2048; idx += NT) {
        int side = idx >> 10, rem = idx & 1023, i = rem >> 6, o = rem & 63;
        sWq[idx] = (side ? kw : qw)[o*16 + i];
    }
    if (tid < 64) { sBias[tid] = qb[tid]; sBias[64 + tid] = kb[tid]; }
    __syncthreads();

    // ---- phase 1: grouped 1x1 Q/K conv (FFMA2)
    for (int t = tid; t < 8192; t += NT) {
        int side = t >> 12, rem = t & 4095, o2 = rem >> 7, x = rem & 127;
        int o = o2*2, g = o >> 4;
        const float* R = side ? sRr : sRl;
        const u64* wp = (const u64*)(sWq + side*1024 + o);
        u64 acc = pk2(sBias[side*64 + o], sBias[side*64 + o + 1]);
#pragma unroll
        for (int i = 0; i < 16; i++) {
            float rv = R[(g*16 + i)*128 + x];
            u64 prv = pk2(rv, rv);
            FMA2(acc, wp[(unsigned)(i*32)], prv);
        }
        float a0, a1; upk2(acc, a0, a1);
        if (side == 0) { sA[x*65 + o] = a0; sA[x*65 + o + 1] = a1; }
        else           { sB[o*132 + x] = a0; sB[(o+1)*132 + x] = a1; }
    }
    __syncthreads();

    // ---- phase 2: per-channel row means, subtract
    for (int task = w; task < 128; task += 32) {
        float s = 0.f;
        if (task < 64) {
#pragma unroll
            for (int k = 0; k < 4; k++) s += sA[(lane + 32*k)*65 + task];
        } else {
#pragma unroll
            for (int k = 0; k < 4; k++) s += sB[(task - 64)*132 + lane + 32*k];
        }
#pragma unroll
        for (int off = 16; off; off >>= 1) s += __shfl_xor_sync(0xffffffffu, s, off);
        if (lane == 0) sMean[task] = s * (1.f/128.f);
    }
    __syncthreads();
    for (int idx = tid; idx < 8192; idx += NT) {
        int c = idx >> 7, u = idx & 127;
        sA[u*65 + c]  -= sMean[c];
        sB[c*132 + u] -= sMean[64 + c];
    }
    __syncthreads();

    // ---- phase 3: score GEMM S[u][v] = sum_c Q[c][u] K[c][v]  (1u x 16v, b broadcast)
    {
        int u0 = lane + 32*(w >> 3);
        int v0 = (w & 7)*16;
        u64 acc2[8];
#pragma unroll
        for (int j = 0; j < 8; j++) acc2[j] = 0ull;
        for (int c = 0; c < 64; c++) {
            float a0 = sA[u0*65 + c];
            u64 pa0 = pk2(a0, a0);
            const ulonglong2* kp = (const ulonglong2*)(sB + c*132 + v0);
            ulonglong2 q0 = kp[0], q1 = kp[1], q2 = kp[2], q3 = kp[3];
            FMA2(acc2[0], pa0, q0.x);
            FMA2(acc2[1], pa0, q0.y);
            FMA2(acc2[2], pa0, q1.x);
            FMA2(acc2[3], pa0, q1.y);
            FMA2(acc2[4], pa0, q2.x);
            FMA2(acc2[5], pa0, q2.y);
            FMA2(acc2[6], pa0, q3.x);
            FMA2(acc2[7], pa0, q3.y);
        }
#pragma unroll
        for (int j = 0; j < 8; j++) {
            float l0, h0;
            upk2(acc2[j], l0, h0);
            sS[u0*SP + v0 + 2*j]     = l0;
            sS[u0*SP + v0 + 2*j + 1] = h0;
        }
    }
    __syncthreads();

    // ---- phase 4a: row softmax -> sM
    for (int r = w; r < 128; r += 32) {
        float x4[4]; float m = -1e30f;
#pragma unroll
        for (int k = 0; k < 4; k++) { x4[k] = sS[r*SP + lane + 32*k]; m = fmaxf(m, x4[k]); }
#pragma unroll
        for (int off = 16; off; off >>= 1) m = fmaxf(m, __shfl_xor_sync(0xffffffffu, m, off));
        float e4[4]; float s = 0.f;
#pragma unroll
        for (int k = 0; k < 4; k++) { e4[k] = __expf(x4[k] - m); s += e4[k]; }
#pragma unroll
        for (int off = 16; off; off >>= 1) s += __shfl_xor_sync(0xffffffffu, s, off);
        float inv = 1.f / s;
#pragma unroll
        for (int k = 0; k < 4; k++) sM[r*SP + lane + 32*k] = e4[k] * inv;
    }
    __syncthreads();
    // ---- phase 4b: col softmax in place in sS (sS[u][v] <- M_lr[v][u])
    for (int c = w; c < 128; c += 32) {
        float x4[4]; float m = -1e30f;
#pragma unroll
        for (int k = 0; k < 4; k++) { x4[k] = sS[(lane + 32*k)*SP + c]; m = fmaxf(m, x4[k]); }
#pragma unroll
        for (int off = 16; off; off >>= 1) m = fmaxf(m, __shfl_xor_sync(0xffffffffu, m, off));
        float e4[4]; float s = 0.f;
#pragma unroll
        for (int k = 0; k < 4; k++) { e4[k] = __expf(x4[k] - m); s += e4[k]; }
#pragma unroll
        for (int off = 16; off; off >>= 1) s += __shfl_xor_sync(0xffffffffu, s, off);
        float inv = 1.f / s;
#pragma unroll
        for (int k = 0; k < 4; k++) sS[(lane + 32*k)*SP + c] = e4[k] * inv;
    }
    __syncthreads();

    // ---- phase 5: validity maps (1024 threads, v-range quartered)
    {
        int task = tid & 255, vq = tid >> 8;
        int side = task >> 7, u = task & 127;
        int vA = vq*32, vB = vA + 32;
        float accv = 0.f;
        if (side == 0) {
            for (int v = vA; v < vB; v++) {
                float A = 0.f;
#pragma unroll
                for (int d = -2; d <= 2; d++) {
                    int uu = u + d;
                    if ((unsigned)uu < 128u) A += sM[uu*SP + v];
                }
                accv += A * sS[u*SP + v];
            }
        } else {
            for (int v = vA; v < vB; v++) {
                float A = 0.f;
#pragma unroll
                for (int d = -2; d <= 2; d++) {
                    int uu = u + d;
                    if ((unsigned)uu < 128u) A += sS[v*SP + uu];
                }
                accv += A * sM[v*SP + u];
            }
        }
        sPart[tid] = accv;
    }
    __syncthreads();
    if (tid < 256) {
        int side = tid >> 7, u = tid & 127;
        sV[side][u] = tanhf(5.f * (sPart[tid] + sPart[tid + 256] + sPart[tid + 512] + sPart[tid + 768]));
    }
    __syncthreads();

    // ---- phase 6: transport GEMMs + blend (2u x 8c, X broadcast)
    {
        int side = w >> 4, wl = w & 15;
        int c0 = (wl & 7)*8, uh = wl >> 3;
        const float* X = side ? sXl : sXr;
        u64 acc2[2][4];
#pragma unroll
        for (int i = 0; i < 2; i++)
#pragma unroll
            for (int j = 0; j < 4; j++) acc2[i][j] = 0ull;

        int u0 = lane + 32*uh;           // u0, u0+64
        for (int v = 0; v < 128; v++) {
            u64 pa[2];
            if (side == 0) {
#pragma unroll
                for (int i = 0; i < 2; i++) {
                    float a = sM[(u0 + 64*i)*SP + v];
                    pa[i] = pk2(a, a);
                }
            } else {
#pragma unroll
                for (int i = 0; i < 2; i++) {
                    float a = sS[v*SP + u0 + 64*i];
                    pa[i] = pk2(a, a);
                }
            }
            const ulonglong2* xp = (const ulonglong2*)(X + v*68 + c0);
            ulonglong2 xA = xp[0], xB = xp[1];
#pragma unroll
            for (int i = 0; i < 2; i++) {
                FMA2(acc2[i][0], pa[i], xA.x);
                FMA2(acc2[i][1], pa[i], xA.y);
                FMA2(acc2[i][2], pa[i], xB.x);
                FMA2(acc2[i][3], pa[i], xB.y);
            }
        }

        float* ob = out + (side ? (long)SZ : 0L) + b*CHW + h*Ww;
        const float* bb = (side ? xr : xl) + b*CHW + h*Ww;
#pragma unroll
        for (int i = 0; i < 2; i++) {
            int u = u0 + 64*i;
            float Vv = sV[side][u];
#pragma unroll
            for (int j = 0; j < 4; j++) {
                float t0, t1;
                upk2(acc2[i][j], t0, t1);
                int c = c0 + 2*j;
                ob[c*HW + u]      = fmaf(bb[c*HW + u],      1.f - Vv, t0*Vv);
                ob[(c+1)*HW + u]  = fmaf(bb[(c+1)*HW + u],  1.f - Vv, t1*Vv);
            }
        }
    }
}

// ---------------- launcher ----------------
extern "C" void kernel_launch(void* const* d_in, const int* in_sizes, int n_in,
                              void* d_out, int out_size) {
    const float* xl    = (const float*)d_in[0];
    const float* xr    = (const float*)d_in[1];
    const float* gamma = (const float*)d_in[2];
    const float* beta  = (const float*)d_in[3];
    const float* rw1   = (const float*)d_in[4];
    const float* rb1   = (const float*)d_in[5];
    const float* rw2   = (const float*)d_in[6];
    const float* rb2   = (const float*)d_in[7];
    const float* qw    = (const float*)d_in[8];
    const float* qb    = (const float*)d_in[9];
    const float* kw    = (const float*)d_in[10];
    const float* kb    = (const float*)d_in[11];
    float* out = (float*)d_out;

    const int CONV_SMEM = (CG*(TH+2)*130 + 2304) * 4;   // 59136

    cudaFuncSetAttribute(k_conv3<true>,  cudaFuncAttributeMaxDynamicSharedMemorySize, CONV_SMEM);
    cudaFuncSetAttribute(k_conv3<false>, cudaFuncAttributeMaxDynamicSharedMemorySize, CONV_SMEM);
    cudaFuncSetAttribute(k_attn,         cudaFuncAttributeMaxDynamicSharedMemorySize, ATT_SMEM);

    k_bnstats<<<dim3(Cc, 2), 256>>>(xl, xr, gamma, beta);
    k_conv3<true ><<<dim3(Hh/TH, Gg, 2*Bn), 256, CONV_SMEM>>>(xl, xr, rw1, rb1);
    k_conv3<false><<<dim3(Hh/TH, Gg, 2*Bn), 256, CONV_SMEM>>>(xl, xr, rw2, rb2);
    k_attn<<<NR, NT, ATT_SMEM>>>(xl, xr, qw, qb, kw, kb, out);
}

// round 8
// speedup vs baseline: 1.7164x; 1.1989x over previous
#include <cuda_runtime.h>
#include <math.h>

#define Bn 8
#define Cc 64
#define Hh 128
#define Ww 128
#define Gg 4
#define CG 16
#define HW (Hh*Ww)          // 16384
#define CHW (Cc*HW)         // 1048576
#define SZ (Bn*CHW)         // 8388608
#define NR (Bn*Hh)          // 1024
#define TH 4
#define SP 129              // sS/sM pitch (odd -> conflict-free column walks)
#define CP 136              // conv sIn pitch: interior at col 4 (16B aligned)
#define CICSZ (6*CP)        // 816 floats per input channel

typedef unsigned long long u64;

__device__ __forceinline__ u64 pk2(float lo, float hi) {
    u64 r;
    asm("mov.b64 %0, {%1, %2};" : "=l"(r)
        : "r"(__float_as_uint(lo)), "r"(__float_as_uint(hi)));
    return r;
}
__device__ __forceinline__ void upk2(u64 p, float& lo, float& hi) {
    unsigned a, bq;
    asm("mov.b64 {%0, %1}, %2;" : "=r"(a), "=r"(bq) : "l"(p));
    lo = __uint_as_float(a); hi = __uint_as_float(bq);
}
#define FMA2(d, a, b) asm("fma.rn.f32x2 %0, %1, %2, %3;" : "=l"(d) : "l"(a), "l"(b), "l"(d))

// scratch (device globals; no allocation allowed)
__device__ float g_t[2*SZ];        // conv1+lrelu outputs
__device__ float g_r[2*SZ];        // resblock outputs
__device__ float g_stats[2][2][Cc];// [side][a|d][c]: bn(x) = a*x + d

// ---------------- BN batch statistics ----------------
__global__ void __launch_bounds__(256) k_bnstats(const float* __restrict__ xl,
                                                 const float* __restrict__ xr,
                                                 const float* __restrict__ gamma,
                                                 const float* __restrict__ beta) {
    int c = blockIdx.x, side = blockIdx.y;
    const float* x = side ? xr : xl;
    int tid = threadIdx.x;
    float s = 0.f, s2 = 0.f;
    for (int b = 0; b < Bn; b++) {
        const float* p = x + b*CHW + c*HW;
        for (int i = tid; i < HW; i += 256) {
            float v = p[i];
            s += v; s2 = fmaf(v, v, s2);
        }
    }
    __shared__ float sh[256], sh2[256];
    sh[tid] = s; sh2[tid] = s2;
    __syncthreads();
    for (int off = 128; off; off >>= 1) {
        if (tid < off) { sh[tid] += sh[tid+off]; sh2[tid] += sh2[tid+off]; }
        __syncthreads();
    }
    if (tid == 0) {
        double N = (double)(Bn*HW);
        double m = (double)sh[0] / N;
        double var = (double)sh2[0] / N - m*m;
        double rstd = 1.0 / sqrt(var + 1e-5);
        float a = gamma[c] * (float)rstd;
        float d = beta[c] - a * (float)m;
        g_stats[side][0][c] = a;
        g_stats[side][1][c] = d;
    }
}

// ---------------- grouped 3x3 conv (FFMA2, fast vector staging) ----------------
template<bool FIRST>
__global__ void __launch_bounds__(256) k_conv3(const float* __restrict__ xl,
                                               const float* __restrict__ xr,
                                               const float* __restrict__ wgt,
                                               const float* __restrict__ bias) {
    int ty = blockIdx.x, g = blockIdx.y;
    int side = blockIdx.z >> 3, b = blockIdx.z & 7;
    const float* xraw = side ? xr : xl;
    const float* in   = FIRST ? xraw : (g_t + side*SZ);
    float* out        = FIRST ? (g_t + side*SZ) : (g_r + side*SZ);

    extern __shared__ float sm[];
    float* sIn = sm;                 // [16][6][136] = 13056
    float* sW2 = sm + 13056;         // [ic][k][o] = 2304
    __shared__ float sa[CG], sd[CG];
    int tid = threadIdx.x;

    if (tid < CG) {
        sa[tid] = g_stats[side][0][g*CG + tid];
        sd[tid] = g_stats[side][1][g*CG + tid];
    }
    __syncthreads();

    // transposed weight load: sW2[(ic*9+k)*16 + o] = wgt[g][o][ic][k]
    for (int i = tid; i < 2304; i += 256) {
        int o = i & 15, rem = i >> 4;
        int k = rem % 9, ic = rem / 9;
        sW2[i] = wgt[g*2304 + (o*16 + ic)*9 + k];
    }

    // halo columns are ALWAYS zero (blocks span full image width)
    for (int i = tid; i < 96; i += 256) {      // 16 ic x 6 r
        int ic = i / 6, r = i - ic*6;
        sIn[ic*CICSZ + r*CP + 3]   = 0.f;
        sIn[ic*CICSZ + r*CP + 132] = 0.f;
    }

    // vector staging: thread -> (x4 = float4 col, rowid), 96 row-slots / 8 row-threads
    {
        int x4 = tid & 31, rowid = tid >> 5;
        int y0 = ty*TH - 1;
        const float* inb = in + b*CHW + g*CG*HW;
#pragma unroll
        for (int s = rowid; s < 96; s += 8) {
            int ic = s / 6, r = s - ic*6;
            int y = y0 + r;
            float4 v4 = make_float4(0.f, 0.f, 0.f, 0.f);
            if ((unsigned)y < (unsigned)Hh) {
                v4 = *(const float4*)(inb + ic*HW + y*Ww + x4*4);
                if (FIRST) {
                    float a = sa[ic], d = sd[ic];
                    v4.x = fmaf(a, v4.x, d);
                    v4.y = fmaf(a, v4.y, d);
                    v4.z = fmaf(a, v4.z, d);
                    v4.w = fmaf(a, v4.w, d);
                }
            }
            *(float4*)(sIn + ic*CICSZ + r*CP + 4 + x4*4) = v4;
        }
    }
    __syncthreads();

    int xcol = tid & 127, half = tid >> 7;
    u64 acc2[4][TH];
#pragma unroll
    for (int o2 = 0; o2 < 4; o2++) {
        u64 bp = pk2(bias[g*CG + half*8 + 2*o2], bias[g*CG + half*8 + 2*o2 + 1]);
#pragma unroll
        for (int r = 0; r < TH; r++) acc2[o2][r] = bp;
    }

    for (int ic = 0; ic < CG; ic++) {
        const float* ip = sIn + ic*CICSZ;
#pragma unroll
        for (int k = 0; k < 9; k++) {
            int dy = k / 3, dx = k - dy*3;
            const ulonglong2* wq = (const ulonglong2*)(sW2 + (ic*9 + k)*16 + half*8);
            ulonglong2 wA = wq[0], wB = wq[1];
#pragma unroll
            for (int r = 0; r < TH; r++) {
                float iv = ip[(r+dy)*CP + xcol + 3 + dx];
                u64 piv = pk2(iv, iv);
                FMA2(acc2[0][r], wA.x, piv);
                FMA2(acc2[1][r], wA.y, piv);
                FMA2(acc2[2][r], wB.x, piv);
                FMA2(acc2[3][r], wB.y, piv);
            }
        }
    }

    int ybase = ty*TH;
#pragma unroll
    for (int o2 = 0; o2 < 4; o2++) {
        int ocl0 = half*8 + 2*o2;
        int gbase = b*CHW + (g*CG + ocl0)*HW + ybase*Ww + xcol;
#pragma unroll
        for (int r = 0; r < TH; r++) {
            float v0, v1;
            upk2(acc2[o2][r], v0, v1);
            if (FIRST) {
                v0 = v0 > 0.f ? v0 : 0.1f*v0;
                v1 = v1 > 0.f ? v1 : 0.1f*v1;
            } else {
                v0 += fmaf(sa[ocl0],   xraw[gbase + r*Ww],      sd[ocl0]);
                v1 += fmaf(sa[ocl0+1], xraw[gbase + HW + r*Ww], sd[ocl0+1]);
            }
            out[gbase + r*Ww]      = v0;
            out[gbase + HW + r*Ww] = v1;
        }
    }
}

// ---------------- fused: QK 1x1 conv + score + dual softmax + validity + transport ----------------
// 1024 threads (32 warps); smem layout unchanged.
#define ATT_SMEM (50688*4)
#define NT 1024
__global__ void __launch_bounds__(NT) k_attn(const float* __restrict__ xl,
                                             const float* __restrict__ xr,
                                             const float* __restrict__ qw, const float* __restrict__ qb,
                                             const float* __restrict__ kw, const float* __restrict__ kb,
                                             float* __restrict__ out) {
    int n = blockIdx.x, b = n >> 7, h = n & 127;
    extern __shared__ float sm[];
    float* sA  = sm;
    float* sB  = sm + 8320;
    float* sS  = sm + 16768;
    float* sXl = sm + 33280;
    float* sXr = sm + 41984;
    float* sM  = sm;                 // overlay (sA+sB dead after score GEMM)
    __shared__ float sWq[2048];      // transposed: [side][i][o]
    __shared__ float sBias[128];
    __shared__ float sMean[128];
    __shared__ float sV[2][128];
    __shared__ float sPart[NT];
    int tid = threadIdx.x, lane = tid & 31, w = tid >> 5;

    // ---- phase 0: load resblock rows (into sS region), x rows, weights
    const float* Rl = g_r + b*CHW + h*Ww;
    const float* Rr = g_r + SZ + b*CHW + h*Ww;
    float* sRl = sS;          // [c][128]
    float* sRr = sS + 8192;
    for (int idx = tid; idx < 8192; idx += NT) {
        int c = idx >> 7, x = idx & 127;
        sRl[idx] = Rl[c*HW + x];
        sRr[idx] = Rr[c*HW + x];
        sXl[x*68 + c] = xl[b*CHW + c*HW + h*Ww + x];
        sXr[x*68 + c] = xr[b*CHW + c*HW + h*Ww + x];
    }
    for (int idx = tid; idx < 2048; idx += NT) {
        int side = idx >> 10, rem = idx & 1023, i = rem >> 6, o = rem & 63;
        sWq[idx] = (side ? kw : qw)[o*16 + i];
    }
    if (tid < 64) { sBias[tid] = qb[tid]; sBias[64 + tid] = kb[tid]; }
    __syncthreads();

    // ---- phase 1: grouped 1x1 Q/K conv (FFMA2)
    for (int t = tid; t < 8192; t += NT) {
        int side = t >> 12, rem = t & 4095, o2 = rem >> 7, x = rem & 127;
        int o = o2*2, g = o >> 4;
        const float* R = side ? sRr : sRl;
        const u64* wp = (const u64*)(sWq + side*1024 + o);
        u64 acc = pk2(sBias[side*64 + o], sBias[side*64 + o + 1]);
#pragma unroll
        for (int i = 0; i < 16; i++) {
            float rv = R[(g*16 + i)*128 + x];
            u64 prv = pk2(rv, rv);
            FMA2(acc, wp[(unsigned)(i*32)], prv);
        }
        float a0, a1; upk2(acc, a0, a1);
        if (side == 0) { sA[x*65 + o] = a0; sA[x*65 + o + 1] = a1; }
        else           { sB[o*132 + x] = a0; sB[(o+1)*132 + x] = a1; }
    }
    __syncthreads();

    // ---- phase 2: per-channel row means, subtract
    for (int task = w; task < 128; task += 32) {
        float s = 0.f;
        if (task < 64) {
#pragma unroll
            for (int k = 0; k < 4; k++) s += sA[(lane + 32*k)*65 + task];
        } else {
#pragma unroll
            for (int k = 0; k < 4; k++) s += sB[(task - 64)*132 + lane + 32*k];
        }
#pragma unroll
        for (int off = 16; off; off >>= 1) s += __shfl_xor_sync(0xffffffffu, s, off);
        if (lane == 0) sMean[task] = s * (1.f/128.f);
    }
    __syncthreads();
    for (int idx = tid; idx < 8192; idx += NT) {
        int c = idx >> 7, u = idx & 127;
        sA[u*65 + c]  -= sMean[c];
        sB[c*132 + u] -= sMean[64 + c];
    }
    __syncthreads();

    // ---- phase 3: score GEMM S[u][v] = sum_c Q[c][u] K[c][v]  (2u x 8v, balanced)
    {
        int uh = w >> 4;                  // 0..1
        int v0 = (w & 15)*8;
        int u0 = lane + 32*uh;            // pair: u0, u0+64
        u64 acc2[2][4];
#pragma unroll
        for (int i = 0; i < 2; i++)
#pragma unroll
            for (int j = 0; j < 4; j++) acc2[i][j] = 0ull;
        for (int c = 0; c < 64; c++) {
            float a0 = sA[u0*65 + c];
            float a1 = sA[(u0+64)*65 + c];
            u64 pa0 = pk2(a0, a0);
            u64 pa1 = pk2(a1, a1);
            const ulonglong2* kp = (const ulonglong2*)(sB + c*132 + v0);
            ulonglong2 q0 = kp[0], q1 = kp[1];
            FMA2(acc2[0][0], pa0, q0.x);
            FMA2(acc2[0][1], pa0, q0.y);
            FMA2(acc2[0][2], pa0, q1.x);
            FMA2(acc2[0][3], pa0, q1.y);
            FMA2(acc2[1][0], pa1, q0.x);
            FMA2(acc2[1][1], pa1, q0.y);
            FMA2(acc2[1][2], pa1, q1.x);
            FMA2(acc2[1][3], pa1, q1.y);
        }
#pragma unroll
        for (int i = 0; i < 2; i++) {
            float* sp = sS + (u0 + 64*i)*SP + v0;
#pragma unroll
            for (int j = 0; j < 4; j++) {
                float l0, h0;
                upk2(acc2[i][j], l0, h0);
                sp[2*j]     = l0;
                sp[2*j + 1] = h0;
            }
        }
    }
    __syncthreads();

    // ---- phase 4a: row softmax -> sM
    for (int r = w; r < 128; r += 32) {
        float x4[4]; float m = -1e30f;
#pragma unroll
        for (int k = 0; k < 4; k++) { x4[k] = sS[r*SP + lane + 32*k]; m = fmaxf(m, x4[k]); }
#pragma unroll
        for (int off = 16; off; off >>= 1) m = fmaxf(m, __shfl_xor_sync(0xffffffffu, m, off));
        float e4[4]; float s = 0.f;
#pragma unroll
        for (int k = 0; k < 4; k++) { e4[k] = __expf(x4[k] - m); s += e4[k]; }
#pragma unroll
        for (int off = 16; off; off >>= 1) s += __shfl_xor_sync(0xffffffffu, s, off);
        float inv = 1.f / s;
#pragma unroll
        for (int k = 0; k < 4; k++) sM[r*SP + lane + 32*k] = e4[k] * inv;
    }
    __syncthreads();
    // ---- phase 4b: col softmax in place in sS (sS[u][v] <- M_lr[v][u])
    for (int c = w; c < 128; c += 32) {
        float x4[4]; float m = -1e30f;
#pragma unroll
        for (int k = 0; k < 4; k++) { x4[k] = sS[(lane + 32*k)*SP + c]; m = fmaxf(m, x4[k]); }
#pragma unroll
        for (int off = 16; off; off >>= 1) m = fmaxf(m, __shfl_xor_sync(0xffffffffu, m, off));
        float e4[4]; float s = 0.f;
#pragma unroll
        for (int k = 0; k < 4; k++) { e4[k] = __expf(x4[k] - m); s += e4[k]; }
#pragma unroll
        for (int off = 16; off; off >>= 1) s += __shfl_xor_sync(0xffffffffu, s, off);
        float inv = 1.f / s;
#pragma unroll
        for (int k = 0; k < 4; k++) sS[(lane + 32*k)*SP + c] = e4[k] * inv;
    }
    __syncthreads();

    // ---- phase 5: validity maps (1024 threads, v-range quartered)
    {
        int task = tid & 255, vq = tid >> 8;
        int side = task >> 7, u = task & 127;
        int vA = vq*32, vB = vA + 32;
        float accv = 0.f;
        if (side == 0) {
            for (int v = vA; v < vB; v++) {
                float A = 0.f;
#pragma unroll
                for (int d = -2; d <= 2; d++) {
                    int uu = u + d;
                    if ((unsigned)uu < 128u) A += sM[uu*SP + v];
                }
                accv += A * sS[u*SP + v];
            }
        } else {
            for (int v = vA; v < vB; v++) {
                float A = 0.f;
#pragma unroll
                for (int d = -2; d <= 2; d++) {
                    int uu = u + d;
                    if ((unsigned)uu < 128u) A += sS[v*SP + uu];
                }
                accv += A * sM[v*SP + u];
            }
        }
        sPart[tid] = accv;
    }
    __syncthreads();
    if (tid < 256) {
        int side = tid >> 7, u = tid & 127;
        sV[side][u] = tanhf(5.f * (sPart[tid] + sPart[tid + 256] + sPart[tid + 512] + sPart[tid + 768]));
    }
    __syncthreads();

    // ---- phase 6: transport GEMMs + blend (2u x 8c, X broadcast)
    {
        int side = w >> 4, wl = w & 15;
        int c0 = (wl & 7)*8, uh = wl >> 3;
        const float* X = side ? sXl : sXr;
        u64 acc2[2][4];
#pragma unroll
        for (int i = 0; i < 2; i++)
#pragma unroll
            for (int j = 0; j < 4; j++) acc2[i][j] = 0ull;

        int u0 = lane + 32*uh;           // u0, u0+64
        for (int v = 0; v < 128; v++) {
            u64 pa[2];
            if (side == 0) {
#pragma unroll
                for (int i = 0; i < 2; i++) {
                    float a = sM[(u0 + 64*i)*SP + v];
                    pa[i] = pk2(a, a);
                }
            } else {
#pragma unroll
                for (int i = 0; i < 2; i++) {
                    float a = sS[v*SP + u0 + 64*i];
                    pa[i] = pk2(a, a);
                }
            }
            const ulonglong2* xp = (const ulonglong2*)(X + v*68 + c0);
            ulonglong2 xA = xp[0], xB = xp[1];
#pragma unroll
            for (int i = 0; i < 2; i++) {
                FMA2(acc2[i][0], pa[i], xA.x);
                FMA2(acc2[i][1], pa[i], xA.y);
                FMA2(acc2[i][2], pa[i], xB.x);
                FMA2(acc2[i][3], pa[i], xB.y);
            }
        }

        float* ob = out + (side ? (long)SZ : 0L) + b*CHW + h*Ww;
        const float* bb = (side ? xr : xl) + b*CHW + h*Ww;
#pragma unroll
        for (int i = 0; i < 2; i++) {
            int u = u0 + 64*i;
            float Vv = sV[side][u];
#pragma unroll
            for (int j = 0; j < 4; j++) {
                float t0, t1;
                upk2(acc2[i][j], t0, t1);
                int c = c0 + 2*j;
                ob[c*HW + u]      = fmaf(bb[c*HW + u],      1.f - Vv, t0*Vv);
                ob[(c+1)*HW + u]  = fmaf(bb[(c+1)*HW + u],  1.f - Vv, t1*Vv);
            }
        }
    }
}

// ---------------- launcher ----------------
extern "C" void kernel_launch(void* const* d_in, const int* in_sizes, int n_in,
                              void* d_out, int out_size) {
    const float* xl    = (const float*)d_in[0];
    const float* xr    = (const float*)d_in[1];
    const float* gamma = (const float*)d_in[2];
    const float* beta  = (const float*)d_in[3];
    const float* rw1   = (const float*)d_in[4];
    const float* rb1   = (const float*)d_in[5];
    const float* rw2   = (const float*)d_in[6];
    const float* rb2   = (const float*)d_in[7];
    const float* qw    = (const float*)d_in[8];
    const float* qb    = (const float*)d_in[9];
    const float* kw    = (const float*)d_in[10];
    const float* kb    = (const float*)d_in[11];
    float* out = (float*)d_out;

    const int CONV_SMEM = (16*CICSZ + 2304) * 4;   // 61440

    cudaFuncSetAttribute(k_conv3<true>,  cudaFuncAttributeMaxDynamicSharedMemorySize, CONV_SMEM);
    cudaFuncSetAttribute(k_conv3<false>, cudaFuncAttributeMaxDynamicSharedMemorySize, CONV_SMEM);
    cudaFuncSetAttribute(k_attn,         cudaFuncAttributeMaxDynamicSharedMemorySize, ATT_SMEM);

    k_bnstats<<<dim3(Cc, 2), 256>>>(xl, xr, gamma, beta);
    k_conv3<true ><<<dim3(Hh/TH, Gg, 2*Bn), 256, CONV_SMEM>>>(xl, xr, rw1, rb1);
    k_conv3<false><<<dim3(Hh/TH, Gg, 2*Bn), 256, CONV_SMEM>>>(xl, xr, rw2, rb2);
    k_attn<<<NR, NT, ATT_SMEM>>>(xl, xr, qw, qb, kw, kb, out);
}

// round 9
// speedup vs baseline: 1.7726x; 1.0327x over previous
#include <cuda_runtime.h>
#include <math.h>

#define Bn 8
#define Cc 64
#define Hh 128
#define Ww 128
#define Gg 4
#define CG 16
#define HW (Hh*Ww)          // 16384
#define CHW (Cc*HW)         // 1048576
#define SZ (Bn*CHW)         // 8388608
#define NR (Bn*Hh)          // 1024
#define TH 4
#define SP 129              // sS/sM pitch (odd -> conflict-free column walks)
#define AP 66               // sA pitch (even -> STS.64 output stores)
#define CP 136              // conv sIn pitch
#define CICSZ (6*CP)

typedef unsigned long long u64;

__device__ __forceinline__ u64 pk2(float lo, float hi) {
    u64 r;
    asm("mov.b64 %0, {%1, %2};" : "=l"(r)
        : "r"(__float_as_uint(lo)), "r"(__float_as_uint(hi)));
    return r;
}
__device__ __forceinline__ void upk2(u64 p, float& lo, float& hi) {
    unsigned a, bq;
    asm("mov.b64 {%0, %1}, %2;" : "=r"(a), "=r"(bq) : "l"(p));
    lo = __uint_as_float(a); hi = __uint_as_float(bq);
}
#define FMA2(d, a, b) asm("fma.rn.f32x2 %0, %1, %2, %3;" : "=l"(d) : "l"(a), "l"(b), "l"(d))

// scratch (device globals; no allocation allowed)
__device__ float g_t[2*SZ];
__device__ float g_r[2*SZ];
__device__ float g_stats[2][2][Cc];

// ---------------- BN batch statistics ----------------
__global__ void __launch_bounds__(256) k_bnstats(const float* __restrict__ xl,
                                                 const float* __restrict__ xr,
                                                 const float* __restrict__ gamma,
                                                 const float* __restrict__ beta) {
    int c = blockIdx.x, side = blockIdx.y;
    const float* x = side ? xr : xl;
    int tid = threadIdx.x;
    float s = 0.f, s2 = 0.f;
    for (int b = 0; b < Bn; b++) {
        const float* p = x + b*CHW + c*HW;
        for (int i = tid; i < HW; i += 256) {
            float v = p[i];
            s += v; s2 = fmaf(v, v, s2);
        }
    }
    __shared__ float sh[256], sh2[256];
    sh[tid] = s; sh2[tid] = s2;
    __syncthreads();
    for (int off = 128; off; off >>= 1) {
        if (tid < off) { sh[tid] += sh[tid+off]; sh2[tid] += sh2[tid+off]; }
        __syncthreads();
    }
    if (tid == 0) {
        double N = (double)(Bn*HW);
        double m = (double)sh[0] / N;
        double var = (double)sh2[0] / N - m*m;
        double rstd = 1.0 / sqrt(var + 1e-5);
        float a = gamma[c] * (float)rstd;
        float d = beta[c] - a * (float)m;
        g_stats[side][0][c] = a;
        g_stats[side][1][c] = d;
    }
}

// ---------------- grouped 3x3 conv (FFMA2, fast vector staging) ----------------
template<bool FIRST>
__global__ void __launch_bounds__(256) k_conv3(const float* __restrict__ xl,
                                               const float* __restrict__ xr,
                                               const float* __restrict__ wgt,
                                               const float* __restrict__ bias) {
    int ty = blockIdx.x, g = blockIdx.y;
    int side = blockIdx.z >> 3, b = blockIdx.z & 7;
    const float* xraw = side ? xr : xl;
    const float* in   = FIRST ? xraw : (g_t + side*SZ);
    float* out        = FIRST ? (g_t + side*SZ) : (g_r + side*SZ);

    extern __shared__ float sm[];
    float* sIn = sm;                 // [16][6][136]
    float* sW2 = sm + 13056;         // [ic][k][o]
    __shared__ float sa[CG], sd[CG];
    int tid = threadIdx.x;

    if (tid < CG) {
        sa[tid] = g_stats[side][0][g*CG + tid];
        sd[tid] = g_stats[side][1][g*CG + tid];
    }
    __syncthreads();

    for (int i = tid; i < 2304; i += 256) {
        int o = i & 15, rem = i >> 4;
        int k = rem % 9, ic = rem / 9;
        sW2[i] = wgt[g*2304 + (o*16 + ic)*9 + k];
    }

    for (int i = tid; i < 96; i += 256) {
        int ic = i / 6, r = i - ic*6;
        sIn[ic*CICSZ + r*CP + 3]   = 0.f;
        sIn[ic*CICSZ + r*CP + 132] = 0.f;
    }

    {
        int x4 = tid & 31, rowid = tid >> 5;
        int y0 = ty*TH - 1;
        const float* inb = in + b*CHW + g*CG*HW;
#pragma unroll
        for (int s = rowid; s < 96; s += 8) {
            int ic = s / 6, r = s - ic*6;
            int y = y0 + r;
            float4 v4 = make_float4(0.f, 0.f, 0.f, 0.f);
            if ((unsigned)y < (unsigned)Hh) {
                v4 = *(const float4*)(inb + ic*HW + y*Ww + x4*4);
                if (FIRST) {
                    float a = sa[ic], d = sd[ic];
                    v4.x = fmaf(a, v4.x, d);
                    v4.y = fmaf(a, v4.y, d);
                    v4.z = fmaf(a, v4.z, d);
                    v4.w = fmaf(a, v4.w, d);
                }
            }
            *(float4*)(sIn + ic*CICSZ + r*CP + 4 + x4*4) = v4;
        }
    }
    __syncthreads();

    int xcol = tid & 127, half = tid >> 7;
    u64 acc2[4][TH];
#pragma unroll
    for (int o2 = 0; o2 < 4; o2++) {
        u64 bp = pk2(bias[g*CG + half*8 + 2*o2], bias[g*CG + half*8 + 2*o2 + 1]);
#pragma unroll
        for (int r = 0; r < TH; r++) acc2[o2][r] = bp;
    }

    for (int ic = 0; ic < CG; ic++) {
        const float* ip = sIn + ic*CICSZ;
#pragma unroll
        for (int k = 0; k < 9; k++) {
            int dy = k / 3, dx = k - dy*3;
            const ulonglong2* wq = (const ulonglong2*)(sW2 + (ic*9 + k)*16 + half*8);
            ulonglong2 wA = wq[0], wB = wq[1];
#pragma unroll
            for (int r = 0; r < TH; r++) {
                float iv = ip[(r+dy)*CP + xcol + 3 + dx];
                u64 piv = pk2(iv, iv);
                FMA2(acc2[0][r], wA.x, piv);
                FMA2(acc2[1][r], wA.y, piv);
                FMA2(acc2[2][r], wB.x, piv);
                FMA2(acc2[3][r], wB.y, piv);
            }
        }
    }

    int ybase = ty*TH;
#pragma unroll
    for (int o2 = 0; o2 < 4; o2++) {
        int ocl0 = half*8 + 2*o2;
        int gbase = b*CHW + (g*CG + ocl0)*HW + ybase*Ww + xcol;
#pragma unroll
        for (int r = 0; r < TH; r++) {
            float v0, v1;
            upk2(acc2[o2][r], v0, v1);
            if (FIRST) {
                v0 = v0 > 0.f ? v0 : 0.1f*v0;
                v1 = v1 > 0.f ? v1 : 0.1f*v1;
            } else {
                v0 += fmaf(sa[ocl0],   xraw[gbase + r*Ww],      sd[ocl0]);
                v1 += fmaf(sa[ocl0+1], xraw[gbase + HW + r*Ww], sd[ocl0+1]);
            }
            out[gbase + r*Ww]      = v0;
            out[gbase + HW + r*Ww] = v1;
        }
    }
}

// ---------------- fused attention ----------------
// smem (floats): sA[128][66]=8448 @0 | sB[64][132]=8448 @8448 | sS[128][129] @16896
//                sXl @33408 | sXr @42112 ; sM[128][129] overlays @0
#define ATT_SMEM (50816*4)
#define NT 1024
__global__ void __launch_bounds__(NT) k_attn(const float* __restrict__ xl,
                                             const float* __restrict__ xr,
                                             const float* __restrict__ qw, const float* __restrict__ qb,
                                             const float* __restrict__ kw, const float* __restrict__ kb,
                                             float* __restrict__ out) {
    int n = blockIdx.x, b = n >> 7, h = n & 127;
    extern __shared__ float sm[];
    float* sA  = sm;
    float* sB  = sm + 8448;
    float* sS  = sm + 16896;
    float* sXl = sm + 33408;
    float* sXr = sm + 42112;
    float* sM  = sm;                 // overlay
    __shared__ float sWq[2048];      // [side][i][o]
    __shared__ float sBias[128];
    __shared__ float sMean[128];
    __shared__ float sV[2][128];
    __shared__ float sPart[NT];
    int tid = threadIdx.x, lane = tid & 31, w = tid >> 5;

    // ---- phase 0: weights/bias (sync), then X staging + QK conv with direct LDG
    for (int idx = tid; idx < 2048; idx += NT) {
        int side = idx >> 10, rem = idx & 1023, i = rem >> 6, o = rem & 63;
        sWq[idx] = (side ? kw : qw)[o*16 + i];
    }
    if (tid < 64) { sBias[tid] = qb[tid]; sBias[64 + tid] = kb[tid]; }
    __syncthreads();

    // X staging
    for (int idx = tid; idx < 8192; idx += NT) {
        int c = idx >> 7, x = idx & 127;
        sXl[x*68 + c] = xl[b*CHW + c*HW + h*Ww + x];
        sXr[x*68 + c] = xr[b*CHW + c*HW + h*Ww + x];
    }

    // ---- phase 1: grouped 1x1 Q/K conv, one thread per (side,g,x), R from global
    {
        int side = tid >> 9, rem = tid & 511;
        int g = rem >> 7, x = rem & 127;
        const float* Rg = (side ? g_r + SZ : g_r) + b*CHW + h*Ww + g*16*HW + x;
        const u64* bp = (const u64*)(sBias + side*64 + g*16);
        u64 acc[8];
#pragma unroll
        for (int j = 0; j < 8; j++) acc[j] = bp[j];
#pragma unroll
        for (int i = 0; i < 16; i++) {
            float rv = Rg[(unsigned)(i*HW)];
            u64 prv = pk2(rv, rv);
            const u64* wp = (const u64*)(sWq + side*1024 + i*64 + g*16);
#pragma unroll
            for (int j = 0; j < 8; j++) FMA2(acc[j], wp[j], prv);
        }
        if (side == 0) {
            u64* dst = (u64*)(sA + x*AP + g*16);
#pragma unroll
            for (int j = 0; j < 8; j++) dst[j] = acc[j];
        } else {
            float* dst = sB + (g*16)*132 + x;
#pragma unroll
            for (int j = 0; j < 8; j++) {
                float a0, a1; upk2(acc[j], a0, a1);
                dst[(2*j)*132]   = a0;
                dst[(2*j+1)*132] = a1;
            }
        }
    }
    __syncthreads();

    // ---- phase 2: per-channel row means, subtract
    for (int task = w; task < 128; task += 32) {
        float s = 0.f;
        if (task < 64) {
#pragma unroll
            for (int k = 0; k < 4; k++) s += sA[(lane + 32*k)*AP + task];
        } else {
#pragma unroll
            for (int k = 0; k < 4; k++) s += sB[(task - 64)*132 + lane + 32*k];
        }
#pragma unroll
        for (int off = 16; off; off >>= 1) s += __shfl_xor_sync(0xffffffffu, s, off);
        if (lane == 0) sMean[task] = s * (1.f/128.f);
    }
    __syncthreads();
    for (int idx = tid; idx < 8192; idx += NT) {
        int c = idx >> 7, u = idx & 127;
        sA[u*AP + c]  -= sMean[c];
        sB[c*132 + u] -= sMean[64 + c];
    }
    __syncthreads();

    // ---- phase 3: score GEMM, warp owns 4 rows; row softmax from regs
    float mrow[4][4];                 // normalized M_rl values, held across sync
    {
        int u0 = w*4;
        int v0 = lane*4;
        u64 acc2[4][2];
#pragma unroll
        for (int r = 0; r < 4; r++) { acc2[r][0] = 0ull; acc2[r][1] = 0ull; }
        for (int c = 0; c < 64; c++) {
            const ulonglong2* kp = (const ulonglong2*)(sB + c*132 + v0);
            ulonglong2 bv = kp[0];
#pragma unroll
            for (int r = 0; r < 4; r++) {
                float a = sA[(u0 + r)*AP + c];     // warp-uniform broadcast
                u64 pa = pk2(a, a);
                FMA2(acc2[r][0], pa, bv.x);
                FMA2(acc2[r][1], pa, bv.y);
            }
        }
#pragma unroll
        for (int r = 0; r < 4; r++) {
            float x4[4];
            upk2(acc2[r][0], x4[0], x4[1]);
            upk2(acc2[r][1], x4[2], x4[3]);
            // store raw S for column softmax
            float* sp = sS + (u0 + r)*SP + v0;
            sp[0] = x4[0]; sp[1] = x4[1]; sp[2] = x4[2]; sp[3] = x4[3];
            // row softmax in registers
            float m = fmaxf(fmaxf(x4[0], x4[1]), fmaxf(x4[2], x4[3]));
#pragma unroll
            for (int off = 16; off; off >>= 1) m = fmaxf(m, __shfl_xor_sync(0xffffffffu, m, off));
            float e0 = __expf(x4[0]-m), e1 = __expf(x4[1]-m), e2 = __expf(x4[2]-m), e3 = __expf(x4[3]-m);
            float s = e0 + e1 + e2 + e3;
#pragma unroll
            for (int off = 16; off; off >>= 1) s += __shfl_xor_sync(0xffffffffu, s, off);
            float inv = 1.f / s;
            mrow[r][0] = e0*inv; mrow[r][1] = e1*inv; mrow[r][2] = e2*inv; mrow[r][3] = e3*inv;
        }
    }
    __syncthreads();

    // ---- phase 4: store M_rl rows from regs (overlay now safe) + column softmax
    {
        int u0 = w*4, v0 = lane*4;
#pragma unroll
        for (int r = 0; r < 4; r++) {
            float* mp = sM + (u0 + r)*SP + v0;
            mp[0] = mrow[r][0]; mp[1] = mrow[r][1]; mp[2] = mrow[r][2]; mp[3] = mrow[r][3];
        }
    }
    for (int c = w; c < 128; c += 32) {
        float x4[4]; float m = -1e30f;
#pragma unroll
        for (int k = 0; k < 4; k++) { x4[k] = sS[(lane + 32*k)*SP + c]; m = fmaxf(m, x4[k]); }
#pragma unroll
        for (int off = 16; off; off >>= 1) m = fmaxf(m, __shfl_xor_sync(0xffffffffu, m, off));
        float e4[4]; float s = 0.f;
#pragma unroll
        for (int k = 0; k < 4; k++) { e4[k] = __expf(x4[k] - m); s += e4[k]; }
#pragma unroll
        for (int off = 16; off; off >>= 1) s += __shfl_xor_sync(0xffffffffu, s, off);
        float inv = 1.f / s;
#pragma unroll
        for (int k = 0; k < 4; k++) sS[(lane + 32*k)*SP + c] = e4[k] * inv;
    }
    __syncthreads();

    // ---- phase 5: validity maps
    {
        int task = tid & 255, vq = tid >> 8;
        int side = task >> 7, u = task & 127;
        int vA = vq*32, vB = vA + 32;
        float accv = 0.f;
        if (side == 0) {
            for (int v = vA; v < vB; v++) {
                float A = 0.f;
#pragma unroll
                for (int d = -2; d <= 2; d++) {
                    int uu = u + d;
                    if ((unsigned)uu < 128u) A += sM[uu*SP + v];
                }
                accv += A * sS[u*SP + v];
            }
        } else {
            for (int v = vA; v < vB; v++) {
                float A = 0.f;
#pragma unroll
                for (int d = -2; d <= 2; d++) {
                    int uu = u + d;
                    if ((unsigned)uu < 128u) A += sS[v*SP + uu];
                }
                accv += A * sM[v*SP + u];
            }
        }
        sPart[tid] = accv;
    }
    __syncthreads();
    if (tid < 256) {
        int side = tid >> 7, u = tid & 127;
        sV[side][u] = tanhf(5.f * (sPart[tid] + sPart[tid + 256] + sPart[tid + 512] + sPart[tid + 768]));
    }
    __syncthreads();

    // ---- phase 6: transport GEMMs + blend (2u x 8c, X broadcast)
    {
        int side = w >> 4, wl = w & 15;
        int c0 = (wl & 7)*8, uh = wl >> 3;
        const float* X = side ? sXl : sXr;
        u64 acc2[2][4];
#pragma unroll
        for (int i = 0; i < 2; i++)
#pragma unroll
            for (int j = 0; j < 4; j++) acc2[i][j] = 0ull;

        int u0 = lane + 32*uh;           // u0, u0+64
        for (int v = 0; v < 128; v++) {
            u64 pa[2];
            if (side == 0) {
#pragma unroll
                for (int i = 0; i < 2; i++) {
                    float a = sM[(u0 + 64*i)*SP + v];
                    pa[i] = pk2(a, a);
                }
            } else {
#pragma unroll
                for (int i = 0; i < 2; i++) {
                    float a = sS[v*SP + u0 + 64*i];
                    pa[i] = pk2(a, a);
                }
            }
            const ulonglong2* xp = (const ulonglong2*)(X + v*68 + c0);
            ulonglong2 xA = xp[0], xB = xp[1];
#pragma unroll
            for (int i = 0; i < 2; i++) {
                FMA2(acc2[i][0], pa[i], xA.x);
                FMA2(acc2[i][1], pa[i], xA.y);
                FMA2(acc2[i][2], pa[i], xB.x);
                FMA2(acc2[i][3], pa[i], xB.y);
            }
        }

        float* ob = out + (side ? (long)SZ : 0L) + b*CHW + h*Ww;
        const float* bb = (side ? xr : xl) + b*CHW + h*Ww;
#pragma unroll
        for (int i = 0; i < 2; i++) {
            int u = u0 + 64*i;
            float Vv = sV[side][u];
#pragma unroll
            for (int j = 0; j < 4; j++) {
                float t0, t1;
                upk2(acc2[i][j], t0, t1);
                int c = c0 + 2*j;
                ob[c*HW + u]      = fmaf(bb[c*HW + u],      1.f - Vv, t0*Vv);
                ob[(c+1)*HW + u]  = fmaf(bb[(c+1)*HW + u],  1.f - Vv, t1*Vv);
            }
        }
    }
}

// ---------------- launcher ----------------
extern "C" void kernel_launch(void* const* d_in, const int* in_sizes, int n_in,
                              void* d_out, int out_size) {
    const float* xl    = (const float*)d_in[0];
    const float* xr    = (const float*)d_in[1];
    const float* gamma = (const float*)d_in[2];
    const float* beta  = (const float*)d_in[3];
    const float* rw1   = (const float*)d_in[4];
    const float* rb1   = (const float*)d_in[5];
    const float* rw2   = (const float*)d_in[6];
    const float* rb2   = (const float*)d_in[7];
    const float* qw    = (const float*)d_in[8];
    const float* qb    = (const float*)d_in[9];
    const float* kw    = (const float*)d_in[10];
    const float* kb    = (const float*)d_in[11];
    float* out = (float*)d_out;

    const int CONV_SMEM = (16*CICSZ + 2304) * 4;   // 61440

    cudaFuncSetAttribute(k_conv3<true>,  cudaFuncAttributeMaxDynamicSharedMemorySize, CONV_SMEM);
    cudaFuncSetAttribute(k_conv3<false>, cudaFuncAttributeMaxDynamicSharedMemorySize, CONV_SMEM);
    cudaFuncSetAttribute(k_attn,         cudaFuncAttributeMaxDynamicSharedMemorySize, ATT_SMEM);

    k_bnstats<<<dim3(Cc, 2), 256>>>(xl, xr, gamma, beta);
    k_conv3<true ><<<dim3(Hh/TH, Gg, 2*Bn), 256, CONV_SMEM>>>(xl, xr, rw1, rb1);
    k_conv3<false><<<dim3(Hh/TH, Gg, 2*Bn), 256, CONV_SMEM>>>(xl, xr, rw2, rb2);
    k_attn<<<NR, NT, ATT_SMEM>>>(xl, xr, qw, qb, kw, kb, out);
}